// round 4
// baseline (speedup 1.0000x reference)
#include <cuda_runtime.h>

// Problem dims
#define T_  2048
#define B_  4
#define C_  1024
#define H_  16
#define DK_ 64
#define M_  (T_*B_)   // 8192 rows for the projections

// Scratch (allocation-free rule: device globals). 32 MB each.
__device__ float g_Q[(size_t)B_*H_*T_*DK_];
__device__ float g_K[(size_t)B_*H_*T_*DK_];
__device__ float g_V[(size_t)B_*H_*T_*DK_];
__device__ float g_AO[(size_t)B_*H_*T_*DK_];

// ---------------------------------------------------------------------------
// Fused QKV projection: out = X @ W^T + b, scattered into [B,H,T,DK].
// X is [T,B,C]; row m = t*B+b contiguous. W is [C_out, C_in] (torch Linear).
// 128x128 tile, 16x16 threads, 8x8 per thread (strided ownership), kt=8.
// ---------------------------------------------------------------------------
__global__ __launch_bounds__(256) void gemm_qkv_kernel(
    const float* __restrict__ q_in, const float* __restrict__ k_in,
    const float* __restrict__ v_in,
    const float* __restrict__ Wq, const float* __restrict__ bq,
    const float* __restrict__ Wk, const float* __restrict__ bk,
    const float* __restrict__ Wv, const float* __restrict__ bv)
{
    __shared__ float As[128][8];
    __shared__ float Ws[128][9];   // pad 9 -> conflict-free strided reads

    const float* X; const float* W; const float* bias; float* dst;
    if (blockIdx.z == 0)      { X = q_in; W = Wq; bias = bq; dst = g_Q; }
    else if (blockIdx.z == 1) { X = k_in; W = Wk; bias = bk; dst = g_K; }
    else                      { X = v_in; W = Wv; bias = bv; dst = g_V; }

    const int tx = threadIdx.x, ty = threadIdx.y;
    const int tid = ty * 16 + tx;
    const int m0 = blockIdx.y * 128, n0 = blockIdx.x * 128;
    const int lr = tid >> 1;            // 0..127
    const int lc = (tid & 1) * 4;       // 0 or 4

    float acc[8][8] = {};

    for (int k0 = 0; k0 < C_; k0 += 8) {
        float4 av = *(const float4*)&X[(size_t)(m0 + lr) * C_ + k0 + lc];
        float4 wv = *(const float4*)&W[(size_t)(n0 + lr) * C_ + k0 + lc];
        *(float4*)&As[lr][lc] = av;            // As rows 32B-aligned
        Ws[lr][lc + 0] = wv.x;                 // padded rows: scalar stores
        Ws[lr][lc + 1] = wv.y;
        Ws[lr][lc + 2] = wv.z;
        Ws[lr][lc + 3] = wv.w;
        __syncthreads();
        #pragma unroll
        for (int kk = 0; kk < 8; kk++) {
            float a[8], w[8];
            #pragma unroll
            for (int i = 0; i < 8; i++) a[i] = As[ty + 16 * i][kk];
            #pragma unroll
            for (int j = 0; j < 8; j++) w[j] = Ws[tx + 16 * j][kk];
            #pragma unroll
            for (int i = 0; i < 8; i++)
                #pragma unroll
                for (int j = 0; j < 8; j++)
                    acc[i][j] += a[i] * w[j];
        }
        __syncthreads();
    }

    #pragma unroll
    for (int i = 0; i < 8; i++) {
        int m = m0 + ty + 16 * i;
        int t = m >> 2, b = m & 3;            // m = t*B + b, B=4
        #pragma unroll
        for (int j = 0; j < 8; j++) {
            int n = n0 + tx + 16 * j;
            int h = n >> 6, d = n & 63;       // n = h*DK + d, DK=64
            dst[(((size_t)(b * H_ + h)) * T_ + t) * DK_ + d] = acc[i][j] + bias[n];
        }
    }
}

// ---------------------------------------------------------------------------
// Flash attention over one (b,h): 64-query block per CTA, 64-key tiles.
// smem: Qs[64*64] | KV[64*65] (K transposed, then reused for V) | Ps[64*64] | mask[64]
// ---------------------------------------------------------------------------
__global__ __launch_bounds__(256) void attn_kernel(const int* __restrict__ mask)
{
    extern __shared__ float sm[];
    float* Qs = sm;                    // 4096 floats, [q][d]
    float* KV = sm + 4096;             // 4160 floats, K: [d][kl] stride 65 / V: [kl][d] stride 65
    float* Ps = sm + 4096 + 4160;      // 4096 floats, [q][k]
    unsigned char* ms = (unsigned char*)(sm + 12352);  // 64 bytes

    const int bh = blockIdx.y;                // b*H + h
    const int b  = bh >> 4;                   // H = 16
    const int q0 = blockIdx.x * 64;
    const float* Qg = g_Q + (size_t)bh * T_ * DK_ + (size_t)q0 * DK_;
    const float* Kg = g_K + (size_t)bh * T_ * DK_;
    const float* Vg = g_V + (size_t)bh * T_ * DK_;

    const int tx = threadIdx.x, ty = threadIdx.y;
    const int tid = ty * 16 + tx;

    // load Q tile (vectorized), pre-scaled by 1/sqrt(DK) = 0.125
    #pragma unroll
    for (int i = 0; i < 4; i++) {
        int idx = (tid + i * 256) * 4;         // float element index
        float4 v = *(const float4*)&Qg[idx];
        v.x *= 0.125f; v.y *= 0.125f; v.z *= 0.125f; v.w *= 0.125f;
        *(float4*)&Qs[idx] = v;
    }

    float O[4][4] = {};
    float mrow[4] = {-1e30f, -1e30f, -1e30f, -1e30f};
    float lrow[4] = {};

    for (int k0 = 0; k0 < T_; k0 += 64) {
        __syncthreads();   // previous iteration's readers of KV/Ps are done

        // load K tile transposed: KV[d*65 + kl]  (vector load, scalar scatter)
        #pragma unroll
        for (int i = 0; i < 4; i++) {
            int idx = (tid + i * 256) * 4;
            int kl = idx >> 6, d = idx & 63;
            float4 v = *(const float4*)&Kg[(size_t)(k0 + kl) * DK_ + d];
            KV[(d + 0) * 65 + kl] = v.x;
            KV[(d + 1) * 65 + kl] = v.y;
            KV[(d + 2) * 65 + kl] = v.z;
            KV[(d + 3) * 65 + kl] = v.w;
        }
        // mask arrives from harness as int32 (bool widened)
        if (tid < 64) ms[tid] = (mask[(size_t)b * T_ + k0 + tid] != 0) ? 1 : 0;
        __syncthreads();

        // S = Q K^T (scaled); strided ownership rows ty+16i, cols tx+16j
        float s[4][4] = {};
        #pragma unroll
        for (int kk = 0; kk < 64; kk++) {
            float qv[4], kv[4];
            #pragma unroll
            for (int i = 0; i < 4; i++) qv[i] = Qs[(ty + 16 * i) * 64 + kk];
            #pragma unroll
            for (int j = 0; j < 4; j++) kv[j] = KV[kk * 65 + tx + 16 * j];
            #pragma unroll
            for (int i = 0; i < 4; i++)
                #pragma unroll
                for (int j = 0; j < 4; j++)
                    s[i][j] += qv[i] * kv[j];
        }

        // mask + online softmax
        bool mk[4];
        #pragma unroll
        for (int j = 0; j < 4; j++) mk[j] = (ms[tx + 16 * j] != 0);

        #pragma unroll
        for (int i = 0; i < 4; i++) {
            float mloc = -1e30f;
            #pragma unroll
            for (int j = 0; j < 4; j++) {
                if (mk[j]) s[i][j] = -1e30f;
                mloc = fmaxf(mloc, s[i][j]);
            }
            #pragma unroll
            for (int off = 8; off > 0; off >>= 1)
                mloc = fmaxf(mloc, __shfl_xor_sync(0xffffffffu, mloc, off));

            float mN = fmaxf(mrow[i], mloc);
            float f  = __expf(mrow[i] - mN);
            mrow[i] = mN;

            float ps = 0.f;
            #pragma unroll
            for (int j = 0; j < 4; j++) {
                float p = __expf(s[i][j] - mN);
                ps += p;
                Ps[(ty + 16 * i) * 64 + tx + 16 * j] = p;
            }
            #pragma unroll
            for (int off = 8; off > 0; off >>= 1)
                ps += __shfl_xor_sync(0xffffffffu, ps, off);

            lrow[i] = lrow[i] * f + ps;
            #pragma unroll
            for (int j = 0; j < 4; j++) O[i][j] *= f;
        }
        __syncthreads();   // Ps complete; K-tile reads done

        // load V tile into the same buffer: KV[kl*65 + d]
        #pragma unroll
        for (int i = 0; i < 4; i++) {
            int idx = (tid + i * 256) * 4;
            int kl = idx >> 6, d = idx & 63;
            float4 v = *(const float4*)&Vg[(size_t)(k0 + kl) * DK_ + d];
            KV[kl * 65 + d + 0] = v.x;
            KV[kl * 65 + d + 1] = v.y;
            KV[kl * 65 + d + 2] = v.z;
            KV[kl * 65 + d + 3] = v.w;
        }
        __syncthreads();

        // O += P @ V
        #pragma unroll
        for (int kk = 0; kk < 64; kk++) {
            float pv[4], vv[4];
            #pragma unroll
            for (int i = 0; i < 4; i++) pv[i] = Ps[(ty + 16 * i) * 64 + kk];
            #pragma unroll
            for (int j = 0; j < 4; j++) vv[j] = KV[kk * 65 + tx + 16 * j];
            #pragma unroll
            for (int i = 0; i < 4; i++)
                #pragma unroll
                for (int j = 0; j < 4; j++)
                    O[i][j] += pv[i] * vv[j];
        }
    }

    float* AOg = g_AO + (size_t)bh * T_ * DK_ + (size_t)q0 * DK_;
    #pragma unroll
    for (int i = 0; i < 4; i++) {
        float inv = 1.0f / lrow[i];
        #pragma unroll
        for (int j = 0; j < 4; j++)
            AOg[(ty + 16 * i) * 64 + tx + 16 * j] = O[i][j] * inv;
    }
}

// ---------------------------------------------------------------------------
// Output projection: out[t,b,:] = concat_h AO[b,h,t,:] @ Wo^T + bo, out [T,B,C]
// 128x128 tile, 8x8 per thread.
// ---------------------------------------------------------------------------
__global__ __launch_bounds__(256) void gemm_out_kernel(
    const float* __restrict__ Wo, const float* __restrict__ bo,
    float* __restrict__ Y)
{
    __shared__ float As[128][8];
    __shared__ float Ws[128][9];

    const int tx = threadIdx.x, ty = threadIdx.y;
    const int tid = ty * 16 + tx;
    const int m0 = blockIdx.y * 128, n0 = blockIdx.x * 128;
    const int lr = tid >> 1;
    const int lc = (tid & 1) * 4;

    float acc[8][8] = {};

    for (int k0 = 0; k0 < C_; k0 += 8) {
        {
            int m = m0 + lr;
            int t = m >> 2, b = m & 3;
            int kg = k0 + lc;
            int h = kg >> 6, d = kg & 63;     // 4 consecutive d within one head
            float4 av = *(const float4*)&g_AO[(((size_t)(b * H_ + h)) * T_ + t) * DK_ + d];
            *(float4*)&As[lr][lc] = av;
            float4 wv = *(const float4*)&Wo[(size_t)(n0 + lr) * C_ + k0 + lc];
            Ws[lr][lc + 0] = wv.x;
            Ws[lr][lc + 1] = wv.y;
            Ws[lr][lc + 2] = wv.z;
            Ws[lr][lc + 3] = wv.w;
        }
        __syncthreads();
        #pragma unroll
        for (int kk = 0; kk < 8; kk++) {
            float a[8], w[8];
            #pragma unroll
            for (int i = 0; i < 8; i++) a[i] = As[ty + 16 * i][kk];
            #pragma unroll
            for (int j = 0; j < 8; j++) w[j] = Ws[tx + 16 * j][kk];
            #pragma unroll
            for (int i = 0; i < 8; i++)
                #pragma unroll
                for (int j = 0; j < 8; j++)
                    acc[i][j] += a[i] * w[j];
        }
        __syncthreads();
    }

    #pragma unroll
    for (int i = 0; i < 8; i++) {
        int m = m0 + ty + 16 * i;
        #pragma unroll
        for (int j = 0; j < 8; j++) {
            int n = n0 + tx + 16 * j;
            Y[(size_t)m * C_ + n] = acc[i][j] + bo[n];
        }
    }
}

// ---------------------------------------------------------------------------
extern "C" void kernel_launch(void* const* d_in, const int* in_sizes, int n_in,
                              void* d_out, int out_size)
{
    const float* query = (const float*)d_in[0];
    const float* key   = (const float*)d_in[1];
    const float* value = (const float*)d_in[2];
    const int*   mask  = (const int*)d_in[3];   // bool [B,T] widened to int32
    const float* Wq = (const float*)d_in[4];
    const float* bq = (const float*)d_in[5];
    const float* Wk = (const float*)d_in[6];
    const float* bk = (const float*)d_in[7];
    const float* Wv = (const float*)d_in[8];
    const float* bv = (const float*)d_in[9];
    const float* Wo = (const float*)d_in[10];
    const float* bo = (const float*)d_in[11];
    float* out = (float*)d_out;

    dim3 blk(16, 16);

    gemm_qkv_kernel<<<dim3(C_ / 128, M_ / 128, 3), blk>>>(
        query, key, value, Wq, bq, Wk, bk, Wv, bv);

    const size_t attn_smem = (size_t)(4096 + 4160 + 4096) * sizeof(float) + 64;
    cudaFuncSetAttribute(attn_kernel, cudaFuncAttributeMaxDynamicSharedMemorySize,
                         (int)attn_smem);
    attn_kernel<<<dim3(T_ / 64, B_ * H_), blk, attn_smem>>>(mask);

    gemm_out_kernel<<<dim3(C_ / 128, M_ / 128), blk>>>(Wo, bo, out);
}

// round 6
// speedup vs baseline: 1.5241x; 1.5241x over previous
#include <cuda_runtime.h>
#include <cuda_bf16.h>
#include <mma.h>

using namespace nvcuda;

// Problem dims
#define T_  2048
#define B_  4
#define C_  1024
#define H_  16
#define DK_ 64
#define M_  (T_*B_)   // 8192 rows for the projections

// ---------------------------------------------------------------------------
// Device-global scratch (allocation-free rule)
// ---------------------------------------------------------------------------
__device__ float g_Q[(size_t)B_*H_*T_*DK_];
__device__ float g_K[(size_t)B_*H_*T_*DK_];
__device__ float g_V[(size_t)B_*H_*T_*DK_];
__device__ float g_AO[(size_t)M_*C_];          // attention out, row-major [m=t*B+b][h*64+d]

// bf16 hi/lo arenas: [q|k|v inputs][Wq|Wk|Wv|Wo][AO]
#define WBASE  ((size_t)3*M_*C_)
#define AOOFF  (WBASE + (size_t)4*C_*C_)
#define ARENA  (AOOFF + (size_t)M_*C_)
__device__ __nv_bfloat16 g_hi[ARENA];
__device__ __nv_bfloat16 g_lo[ARENA];

// ---------------------------------------------------------------------------
// fp32 -> (bf16 hi, bf16 lo) split conversion into the arenas.
// ---------------------------------------------------------------------------
__global__ __launch_bounds__(256) void convert_kernel(
    const float* __restrict__ src_in, int use_ao, size_t off, size_t n)
{
    const float* src = use_ao ? g_AO : src_in;
    __nv_bfloat16* hp = g_hi + off;
    __nv_bfloat16* lp = g_lo + off;
    size_t i = ((size_t)blockIdx.x * blockDim.x + threadIdx.x) * 4;
    if (i >= n) return;
    float4 v = *(const float4*)(src + i);
    __nv_bfloat16 h0 = __float2bfloat16(v.x), h1 = __float2bfloat16(v.y);
    __nv_bfloat16 h2 = __float2bfloat16(v.z), h3 = __float2bfloat16(v.w);
    __nv_bfloat16 l0 = __float2bfloat16(v.x - __bfloat162float(h0));
    __nv_bfloat16 l1 = __float2bfloat16(v.y - __bfloat162float(h1));
    __nv_bfloat16 l2 = __float2bfloat16(v.z - __bfloat162float(h2));
    __nv_bfloat16 l3 = __float2bfloat16(v.w - __bfloat162float(h3));
    ushort4 hv = make_ushort4(__bfloat16_as_ushort(h0), __bfloat16_as_ushort(h1),
                              __bfloat16_as_ushort(h2), __bfloat16_as_ushort(h3));
    ushort4 lv = make_ushort4(__bfloat16_as_ushort(l0), __bfloat16_as_ushort(l1),
                              __bfloat16_as_ushort(l2), __bfloat16_as_ushort(l3));
    *(ushort4*)(hp + i) = hv;
    *(ushort4*)(lp + i) = lv;
}

// ---------------------------------------------------------------------------
// WMMA bf16x3 GEMM: D[128,128] = A[128,K] * B[128,K]^T  (K=1024), fp32 accum.
// MODE 0: A = X(q/k/v by blockIdx.z), B = Wq/Wk/Wv; scatter to g_Q/K/V + bias
// MODE 1: A = AO, B = Wo; Y[m*C+n] = D + bo
//
// CTA: 256 threads = 8 warps; warp (wm = wid&3, wn = wid>>2) owns rows
// [32*wm, +32) x cols [64*wn, +64)  -> 2x4 wmma 16x16 tiles.
// K staged in 64-element chunks: Ah/Al/Bh/Bl each [128][72] bf16 in smem.
// ---------------------------------------------------------------------------
#define LDS_  72                       // bf16 row stride (mult of 8)
#define BUFSZ ((size_t)128 * LDS_)     // 9216 bf16 = 18432 B
#define SM_GEMM_BYTES (4 * 128 * LDS_ * 2)   // 73728 B (>= float staging 34816)
#define LDD_  68                       // fp32 staging row stride (mult of 4)

template<int MODE>
__global__ __launch_bounds__(256) void mma_gemm(
    const float* __restrict__ bias_q, const float* __restrict__ bias_k,
    const float* __restrict__ bias_v, float* __restrict__ Y)
{
    extern __shared__ char smc[];
    __nv_bfloat16* Ah = (__nv_bfloat16*)smc;
    __nv_bfloat16* Al = Ah + BUFSZ;
    __nv_bfloat16* Bh = Al + BUFSZ;
    __nv_bfloat16* Bl = Bh + BUFSZ;
    float* Dst = (float*)smc;          // epilogue staging (reuses buffers)

    const int tid = threadIdx.x;
    const int wid = tid >> 5;
    const int wm = wid & 3, wn = wid >> 2;
    const int m0 = blockIdx.y * 128, n0 = blockIdx.x * 128;

    size_t aoff, boff;
    const float* bias;
    if (MODE == 0) {
        int z = blockIdx.z;
        aoff = (size_t)z * M_ * C_;
        boff = WBASE + (size_t)z * C_ * C_;
        bias = (z == 0) ? bias_q : (z == 1) ? bias_k : bias_v;
    } else {
        aoff = AOOFF;
        boff = WBASE + (size_t)3 * C_ * C_;
        bias = bias_q;   // bo
    }
    const __nv_bfloat16* gAh = g_hi + aoff;
    const __nv_bfloat16* gAl = g_lo + aoff;
    const __nv_bfloat16* gBh = g_hi + boff;
    const __nv_bfloat16* gBl = g_lo + boff;

    wmma::fragment<wmma::accumulator, 16, 16, 16, float> acc[2][4];
    #pragma unroll
    for (int i = 0; i < 2; i++)
        #pragma unroll
        for (int j = 0; j < 4; j++)
            wmma::fill_fragment(acc[i][j], 0.0f);

    for (int kc = 0; kc < C_; kc += 64) {
        // stage 64-wide k-chunk of A and B (hi+lo): 4 x 1024 uint4, 16/thread
        #pragma unroll
        for (int t4 = 0; t4 < 4; t4++) {
            int id = tid + t4 * 256;          // 0..1023
            int r  = id >> 3;                 // row 0..127
            int c8 = id & 7;                  // 8-elem group
            size_t ga = (size_t)(m0 + r) * C_ + kc + c8 * 8;
            size_t gb = (size_t)(n0 + r) * C_ + kc + c8 * 8;
            int so = r * LDS_ + c8 * 8;
            *(uint4*)(Ah + so) = *(const uint4*)(gAh + ga);
            *(uint4*)(Al + so) = *(const uint4*)(gAl + ga);
            *(uint4*)(Bh + so) = *(const uint4*)(gBh + gb);
            *(uint4*)(Bl + so) = *(const uint4*)(gBl + gb);
        }
        __syncthreads();

        #pragma unroll
        for (int ks = 0; ks < 4; ks++) {      // 4 x K=16
            int kk = ks * 16;
            wmma::fragment<wmma::matrix_a, 16, 16, 16, __nv_bfloat16, wmma::row_major> a_hi[2], a_lo[2];
            wmma::fragment<wmma::matrix_b, 16, 16, 16, __nv_bfloat16, wmma::col_major> b_hi[4], b_lo[4];
            #pragma unroll
            for (int i = 0; i < 2; i++) {
                int mrow = wm * 32 + i * 16;
                wmma::load_matrix_sync(a_hi[i], Ah + mrow * LDS_ + kk, LDS_);
                wmma::load_matrix_sync(a_lo[i], Al + mrow * LDS_ + kk, LDS_);
            }
            #pragma unroll
            for (int j = 0; j < 4; j++) {
                int ncol = wn * 64 + j * 16;
                wmma::load_matrix_sync(b_hi[j], Bh + ncol * LDS_ + kk, LDS_);
                wmma::load_matrix_sync(b_lo[j], Bl + ncol * LDS_ + kk, LDS_);
            }
            #pragma unroll
            for (int i = 0; i < 2; i++)
                #pragma unroll
                for (int j = 0; j < 4; j++) {
                    wmma::mma_sync(acc[i][j], a_hi[i], b_hi[j], acc[i][j]);
                    wmma::mma_sync(acc[i][j], a_hi[i], b_lo[j], acc[i][j]);
                    wmma::mma_sync(acc[i][j], a_lo[i], b_hi[j], acc[i][j]);
                }
        }
        __syncthreads();
    }

    // Epilogue in two 64-col halves via fp32 smem staging.
    #pragma unroll
    for (int half = 0; half < 2; half++) {
        // warps with wn == half own this half's columns
        if (wn == half) {
            #pragma unroll
            for (int i = 0; i < 2; i++)
                #pragma unroll
                for (int j = 0; j < 4; j++)
                    wmma::store_matrix_sync(
                        Dst + (wm * 32 + i * 16) * LDD_ + j * 16,
                        acc[i][j], LDD_, wmma::mem_row_major);
        }
        __syncthreads();
        // scatter 128 x 64 with bias
        #pragma unroll
        for (int t = 0; t < 32; t++) {
            int id = tid + t * 256;           // 0..8191
            int r = id >> 6, c = id & 63;
            int m = m0 + r;
            int n = n0 + half * 64 + c;
            float v = Dst[r * LDD_ + c] + bias[n];
            if (MODE == 0) {
                int tt = m >> 2, b = m & 3;   // m = t*B + b
                int h = n >> 6, d = n & 63;
                float* dst = (blockIdx.z == 0) ? g_Q : (blockIdx.z == 1) ? g_K : g_V;
                dst[(((size_t)(b * H_ + h)) * T_ + tt) * DK_ + d] = v;
            } else {
                Y[(size_t)m * C_ + n] = v;
            }
        }
        __syncthreads();
    }
}

// ---------------------------------------------------------------------------
// Flash attention (FFMA), 64-query block per CTA, 64-key tiles.
// Writes AO row-major [m = t*B+b][h*64+d] for the out-projection.
// ---------------------------------------------------------------------------
__global__ __launch_bounds__(256) void attn_kernel(const int* __restrict__ mask)
{
    extern __shared__ float sm[];
    float* Qs = sm;                    // 4096 floats, [q][d]
    float* KV = sm + 4096;             // 4160 floats, K: [d][kl] s65 / V: [kl][d] s65
    float* Ps = sm + 4096 + 4160;      // 4096 floats, [q][k]
    unsigned char* ms = (unsigned char*)(sm + 12352);

    const int bh = blockIdx.y;
    const int b  = bh >> 4;
    const int h  = bh & 15;
    const int q0 = blockIdx.x * 64;
    const float* Qg = g_Q + (size_t)bh * T_ * DK_ + (size_t)q0 * DK_;
    const float* Kg = g_K + (size_t)bh * T_ * DK_;
    const float* Vg = g_V + (size_t)bh * T_ * DK_;

    const int tx = threadIdx.x, ty = threadIdx.y;
    const int tid = ty * 16 + tx;

    #pragma unroll
    for (int i = 0; i < 4; i++) {
        int idx = (tid + i * 256) * 4;
        float4 v = *(const float4*)&Qg[idx];
        v.x *= 0.125f; v.y *= 0.125f; v.z *= 0.125f; v.w *= 0.125f;
        *(float4*)&Qs[idx] = v;
    }

    float O[4][4] = {};
    float mrow[4] = {-1e30f, -1e30f, -1e30f, -1e30f};
    float lrow[4] = {};

    for (int k0 = 0; k0 < T_; k0 += 64) {
        __syncthreads();
        #pragma unroll
        for (int i = 0; i < 4; i++) {
            int idx = (tid + i * 256) * 4;
            int kl = idx >> 6, d = idx & 63;
            float4 v = *(const float4*)&Kg[(size_t)(k0 + kl) * DK_ + d];
            KV[(d + 0) * 65 + kl] = v.x;
            KV[(d + 1) * 65 + kl] = v.y;
            KV[(d + 2) * 65 + kl] = v.z;
            KV[(d + 3) * 65 + kl] = v.w;
        }
        if (tid < 64) ms[tid] = (mask[(size_t)b * T_ + k0 + tid] != 0) ? 1 : 0;
        __syncthreads();

        float s[4][4] = {};
        #pragma unroll
        for (int kk = 0; kk < 64; kk++) {
            float qv[4], kv[4];
            #pragma unroll
            for (int i = 0; i < 4; i++) qv[i] = Qs[(ty + 16 * i) * 64 + kk];
            #pragma unroll
            for (int j = 0; j < 4; j++) kv[j] = KV[kk * 65 + tx + 16 * j];
            #pragma unroll
            for (int i = 0; i < 4; i++)
                #pragma unroll
                for (int j = 0; j < 4; j++)
                    s[i][j] += qv[i] * kv[j];
        }

        bool mk[4];
        #pragma unroll
        for (int j = 0; j < 4; j++) mk[j] = (ms[tx + 16 * j] != 0);

        #pragma unroll
        for (int i = 0; i < 4; i++) {
            float mloc = -1e30f;
            #pragma unroll
            for (int j = 0; j < 4; j++) {
                if (mk[j]) s[i][j] = -1e30f;
                mloc = fmaxf(mloc, s[i][j]);
            }
            #pragma unroll
            for (int off = 8; off > 0; off >>= 1)
                mloc = fmaxf(mloc, __shfl_xor_sync(0xffffffffu, mloc, off));

            float mN = fmaxf(mrow[i], mloc);
            float f  = __expf(mrow[i] - mN);
            mrow[i] = mN;

            float ps = 0.f;
            #pragma unroll
            for (int j = 0; j < 4; j++) {
                float p = __expf(s[i][j] - mN);
                ps += p;
                Ps[(ty + 16 * i) * 64 + tx + 16 * j] = p;
            }
            #pragma unroll
            for (int off = 8; off > 0; off >>= 1)
                ps += __shfl_xor_sync(0xffffffffu, ps, off);

            lrow[i] = lrow[i] * f + ps;
            #pragma unroll
            for (int j = 0; j < 4; j++) O[i][j] *= f;
        }
        __syncthreads();

        #pragma unroll
        for (int i = 0; i < 4; i++) {
            int idx = (tid + i * 256) * 4;
            int kl = idx >> 6, d = idx & 63;
            float4 v = *(const float4*)&Vg[(size_t)(k0 + kl) * DK_ + d];
            KV[kl * 65 + d + 0] = v.x;
            KV[kl * 65 + d + 1] = v.y;
            KV[kl * 65 + d + 2] = v.z;
            KV[kl * 65 + d + 3] = v.w;
        }
        __syncthreads();

        #pragma unroll
        for (int kk = 0; kk < 64; kk++) {
            float pv[4], vv[4];
            #pragma unroll
            for (int i = 0; i < 4; i++) pv[i] = Ps[(ty + 16 * i) * 64 + kk];
            #pragma unroll
            for (int j = 0; j < 4; j++) vv[j] = KV[kk * 65 + tx + 16 * j];
            #pragma unroll
            for (int i = 0; i < 4; i++)
                #pragma unroll
                for (int j = 0; j < 4; j++)
                    O[i][j] += pv[i] * vv[j];
        }
    }

    // AO row-major: row m = t*B + b, col = h*64 + d
    #pragma unroll
    for (int i = 0; i < 4; i++) {
        float inv = 1.0f / lrow[i];
        int t = q0 + ty + 16 * i;
        #pragma unroll
        for (int j = 0; j < 4; j++)
            g_AO[(size_t)(t * B_ + b) * C_ + h * DK_ + tx + 16 * j] = O[i][j] * inv;
    }
}

// ---------------------------------------------------------------------------
extern "C" void kernel_launch(void* const* d_in, const int* in_sizes, int n_in,
                              void* d_out, int out_size)
{
    const float* query = (const float*)d_in[0];
    const float* key   = (const float*)d_in[1];
    const float* value = (const float*)d_in[2];
    const int*   mask  = (const int*)d_in[3];
    const float* Wq = (const float*)d_in[4];
    const float* bq = (const float*)d_in[5];
    const float* Wk = (const float*)d_in[6];
    const float* bk = (const float*)d_in[7];
    const float* Wv = (const float*)d_in[8];
    const float* bv = (const float*)d_in[9];
    const float* Wo = (const float*)d_in[10];
    const float* bo = (const float*)d_in[11];
    float* out = (float*)d_out;

    const size_t nX = (size_t)M_ * C_;     // 8388608
    const size_t nW = (size_t)C_ * C_;     // 1048576

    // split-convert inputs and weights
    convert_kernel<<<(unsigned)(nX / 1024), 256>>>(query, 0, 0 * nX, nX);
    convert_kernel<<<(unsigned)(nX / 1024), 256>>>(key,   0, 1 * nX, nX);
    convert_kernel<<<(unsigned)(nX / 1024), 256>>>(value, 0, 2 * nX, nX);
    convert_kernel<<<(unsigned)(nW / 1024), 256>>>(Wq, 0, WBASE + 0 * nW, nW);
    convert_kernel<<<(unsigned)(nW / 1024), 256>>>(Wk, 0, WBASE + 1 * nW, nW);
    convert_kernel<<<(unsigned)(nW / 1024), 256>>>(Wv, 0, WBASE + 2 * nW, nW);
    convert_kernel<<<(unsigned)(nW / 1024), 256>>>(Wo, 0, WBASE + 3 * nW, nW);

    cudaFuncSetAttribute(mma_gemm<0>, cudaFuncAttributeMaxDynamicSharedMemorySize, SM_GEMM_BYTES);
    cudaFuncSetAttribute(mma_gemm<1>, cudaFuncAttributeMaxDynamicSharedMemorySize, SM_GEMM_BYTES);

    // QKV projections on tensor cores (WMMA bf16x3)
    mma_gemm<0><<<dim3(C_ / 128, M_ / 128, 3), 256, SM_GEMM_BYTES>>>(bq, bk, bv, nullptr);

    // attention (FFMA)
    const size_t attn_smem = (size_t)(4096 + 4160 + 4096) * sizeof(float) + 64;
    cudaFuncSetAttribute(attn_kernel, cudaFuncAttributeMaxDynamicSharedMemorySize,
                         (int)attn_smem);
    attn_kernel<<<dim3(T_ / 64, B_ * H_), dim3(16, 16), attn_smem>>>(mask);

    // convert AO, then output projection on tensor cores
    convert_kernel<<<(unsigned)(nX / 1024), 256>>>(nullptr, 1, AOOFF, nX);
    mma_gemm<1><<<dim3(C_ / 128, M_ / 128, 1), 256, SM_GEMM_BYTES>>>(bo, nullptr, nullptr, out);
}

// round 8
// speedup vs baseline: 2.3710x; 1.5557x over previous
#include <cuda_runtime.h>
#include <cuda_bf16.h>
#include <mma.h>

using namespace nvcuda;

// Problem dims
#define T_  2048
#define B_  4
#define C_  1024
#define H_  16
#define DK_ 64
#define M_  (T_*B_)

#define nX ((size_t)M_*C_)
#define nW ((size_t)C_*C_)
#define WBASE  (3*nX)
#define AOOFF  (WBASE + 4*nW)
#define QATT   (AOOFF + nX)
#define KATT   (QATT + nX)
#define VATT   (KATT + nX)
#define ARENA  (VATT + nX)

// bf16 hi/lo arenas (allocation-free rule: device globals)
__device__ __nv_bfloat16 g_hi[ARENA];
__device__ __nv_bfloat16 g_lo[ARENA];

// ---------------------------------------------------------------------------
// helpers
// ---------------------------------------------------------------------------
__device__ __forceinline__ void mma16816(float* c, const unsigned* a, const unsigned* b) {
    asm volatile(
        "mma.sync.aligned.m16n8k16.row.col.f32.bf16.bf16.f32 "
        "{%0,%1,%2,%3}, {%4,%5,%6,%7}, {%8,%9}, {%0,%1,%2,%3};\n"
        : "+f"(c[0]), "+f"(c[1]), "+f"(c[2]), "+f"(c[3])
        : "r"(a[0]), "r"(a[1]), "r"(a[2]), "r"(a[3]), "r"(b[0]), "r"(b[1]));
}
__device__ __forceinline__ unsigned packbf(float lo, float hi) {
    unsigned r;
    asm("cvt.rn.bf16x2.f32 %0, %1, %2;" : "=r"(r) : "f"(hi), "f"(lo));
    return r;
}
__device__ __forceinline__ float lobf(unsigned u) { return __int_as_float(u << 16); }
__device__ __forceinline__ float hibf(unsigned u) { return __int_as_float(u & 0xFFFF0000u); }

// fast exp on the FMA pipe (no MUFU): 2^(x*log2e), deg-5, ~2e-6 rel
__device__ __forceinline__ float fexp(float x) {
    x = fmaxf(x, -87.0f);
    float t  = x * 1.4426950408889634f;
    float fk = t + 12582912.0f;                       // round-to-nearest int
    int   ki = __float_as_int(fk) - 0x4B400000;
    float r  = t - (fk - 12582912.0f);                // r in [-0.5, 0.5]
    float p  = 1.3333558146e-3f;
    p = fmaf(p, r, 9.6181291076e-3f);
    p = fmaf(p, r, 5.5504108664e-2f);
    p = fmaf(p, r, 2.4022650696e-1f);
    p = fmaf(p, r, 6.9314718056e-1f);
    p = fmaf(p, r, 1.0f);
    return p * __int_as_float((ki + 127) << 23);
}

// ---------------------------------------------------------------------------
// fp32 -> (bf16 hi, bf16 lo) split conversion
// ---------------------------------------------------------------------------
__global__ __launch_bounds__(256) void convert_kernel(
    const float* __restrict__ src, size_t off, size_t n)
{
    __nv_bfloat16* hp = g_hi + off;
    __nv_bfloat16* lp = g_lo + off;
    size_t i = ((size_t)blockIdx.x * blockDim.x + threadIdx.x) * 4;
    if (i >= n) return;
    float4 v = *(const float4*)(src + i);
    __nv_bfloat16 h0 = __float2bfloat16(v.x), h1 = __float2bfloat16(v.y);
    __nv_bfloat16 h2 = __float2bfloat16(v.z), h3 = __float2bfloat16(v.w);
    __nv_bfloat16 l0 = __float2bfloat16(v.x - __bfloat162float(h0));
    __nv_bfloat16 l1 = __float2bfloat16(v.y - __bfloat162float(h1));
    __nv_bfloat16 l2 = __float2bfloat16(v.z - __bfloat162float(h2));
    __nv_bfloat16 l3 = __float2bfloat16(v.w - __bfloat162float(h3));
    *(ushort4*)(hp + i) = make_ushort4(__bfloat16_as_ushort(h0), __bfloat16_as_ushort(h1),
                                       __bfloat16_as_ushort(h2), __bfloat16_as_ushort(h3));
    *(ushort4*)(lp + i) = make_ushort4(__bfloat16_as_ushort(l0), __bfloat16_as_ushort(l1),
                                       __bfloat16_as_ushort(l2), __bfloat16_as_ushort(l3));
}

// ---------------------------------------------------------------------------
// WMMA bf16x3 GEMM: D[128,128] = A[128,K] * B[128,K]^T  (K=1024), fp32 accum.
// MODE 0: A = X(q/k/v by z), B = Wq/Wk/Wv; write bf16 hi/lo to QATT/KATT/VATT
//         (Q scaled by 0.125), layout [bh][t][d].
// MODE 1: A = AO (hi/lo at AOOFF), B = Wo; Y = D + bo (fp32 out).
// ---------------------------------------------------------------------------
#define LDS_  72
#define BUFSZ ((size_t)128 * LDS_)
#define SM_GEMM_BYTES (4 * 128 * LDS_ * 2)
#define LDD_  68

template<int MODE>
__global__ __launch_bounds__(256) void mma_gemm(
    const float* __restrict__ bias_q, const float* __restrict__ bias_k,
    const float* __restrict__ bias_v, float* __restrict__ Y)
{
    extern __shared__ char smc[];
    __nv_bfloat16* Ah = (__nv_bfloat16*)smc;
    __nv_bfloat16* Al = Ah + BUFSZ;
    __nv_bfloat16* Bh = Al + BUFSZ;
    __nv_bfloat16* Bl = Bh + BUFSZ;
    float* Dst = (float*)smc;

    const int tid = threadIdx.x;
    const int wid = tid >> 5;
    const int wm = wid & 3, wn = wid >> 2;
    const int m0 = blockIdx.y * 128, n0 = blockIdx.x * 128;

    size_t aoff, boff;
    const float* bias;
    if (MODE == 0) {
        int z = blockIdx.z;
        aoff = (size_t)z * nX;
        boff = WBASE + (size_t)z * nW;
        bias = (z == 0) ? bias_q : (z == 1) ? bias_k : bias_v;
    } else {
        aoff = AOOFF;
        boff = WBASE + 3 * nW;
        bias = bias_q;   // bo
    }
    const __nv_bfloat16* gAh = g_hi + aoff;
    const __nv_bfloat16* gAl = g_lo + aoff;
    const __nv_bfloat16* gBh = g_hi + boff;
    const __nv_bfloat16* gBl = g_lo + boff;

    wmma::fragment<wmma::accumulator, 16, 16, 16, float> acc[2][4];
    #pragma unroll
    for (int i = 0; i < 2; i++)
        #pragma unroll
        for (int j = 0; j < 4; j++)
            wmma::fill_fragment(acc[i][j], 0.0f);

    for (int kc = 0; kc < C_; kc += 64) {
        #pragma unroll
        for (int t4 = 0; t4 < 4; t4++) {
            int id = tid + t4 * 256;
            int r  = id >> 3, c8 = id & 7;
            size_t ga = (size_t)(m0 + r) * C_ + kc + c8 * 8;
            size_t gb = (size_t)(n0 + r) * C_ + kc + c8 * 8;
            int so = r * LDS_ + c8 * 8;
            *(uint4*)(Ah + so) = *(const uint4*)(gAh + ga);
            *(uint4*)(Al + so) = *(const uint4*)(gAl + ga);
            *(uint4*)(Bh + so) = *(const uint4*)(gBh + gb);
            *(uint4*)(Bl + so) = *(const uint4*)(gBl + gb);
        }
        __syncthreads();

        #pragma unroll
        for (int ks = 0; ks < 4; ks++) {
            int kk = ks * 16;
            wmma::fragment<wmma::matrix_a, 16, 16, 16, __nv_bfloat16, wmma::row_major> a_hi[2], a_lo[2];
            wmma::fragment<wmma::matrix_b, 16, 16, 16, __nv_bfloat16, wmma::col_major> b_hi[4], b_lo[4];
            #pragma unroll
            for (int i = 0; i < 2; i++) {
                int mrow = wm * 32 + i * 16;
                wmma::load_matrix_sync(a_hi[i], Ah + mrow * LDS_ + kk, LDS_);
                wmma::load_matrix_sync(a_lo[i], Al + mrow * LDS_ + kk, LDS_);
            }
            #pragma unroll
            for (int j = 0; j < 4; j++) {
                int ncol = wn * 64 + j * 16;
                wmma::load_matrix_sync(b_hi[j], Bh + ncol * LDS_ + kk, LDS_);
                wmma::load_matrix_sync(b_lo[j], Bl + ncol * LDS_ + kk, LDS_);
            }
            #pragma unroll
            for (int i = 0; i < 2; i++)
                #pragma unroll
                for (int j = 0; j < 4; j++) {
                    wmma::mma_sync(acc[i][j], a_hi[i], b_hi[j], acc[i][j]);
                    wmma::mma_sync(acc[i][j], a_hi[i], b_lo[j], acc[i][j]);
                    wmma::mma_sync(acc[i][j], a_lo[i], b_hi[j], acc[i][j]);
                }
        }
        __syncthreads();
    }

    // Epilogue in two 64-col halves via fp32 smem staging.
    #pragma unroll
    for (int half = 0; half < 2; half++) {
        if (wn == half) {
            #pragma unroll
            for (int i = 0; i < 2; i++)
                #pragma unroll
                for (int j = 0; j < 4; j++)
                    wmma::store_matrix_sync(
                        Dst + (wm * 32 + i * 16) * LDD_ + j * 16,
                        acc[i][j], LDD_, wmma::mem_row_major);
        }
        __syncthreads();
        #pragma unroll
        for (int t = 0; t < 32; t++) {
            int id = tid + t * 256;
            int r = id >> 6, c = id & 63;
            int m = m0 + r;
            int n = n0 + half * 64 + c;
            float v = Dst[r * LDD_ + c] + bias[n];
            if (MODE == 0) {
                int z = blockIdx.z;
                if (z == 0) v *= 0.125f;          // fold 1/sqrt(DK) into Q
                int tt = m >> 2, b = m & 3;       // m = t*B + b
                int hh = n >> 6, d = n & 63;
                __nv_bfloat16 hv = __float2bfloat16(v);
                __nv_bfloat16 lv = __float2bfloat16(v - __bfloat162float(hv));
                size_t base = (z == 0) ? QATT : (z == 1) ? KATT : VATT;
                size_t adr = base + (((size_t)(b * H_ + hh)) * T_ + tt) * DK_ + d;
                g_hi[adr] = hv;
                g_lo[adr] = lv;
            } else {
                Y[(size_t)m * C_ + n] = v;
            }
        }
        __syncthreads();
    }
}

// ---------------------------------------------------------------------------
// FA2-style attention on mma.sync bf16x3, poly exp on FMA pipe.
// CTA: 128 queries x (b,h); 256 threads = 8 warps, warp owns 16 q-rows.
// Key tiles of 128. Writes AO bf16 hi/lo directly to arena (row-major [m][C]).
// ---------------------------------------------------------------------------
#define LQK 72
#define LVT 136
#define SQ_H 0
#define SQ_L 9216
#define SK_H 18432
#define SK_L 27648
#define SV_H 36864
#define SV_L 45568
#define SMEM_ELEMS 54272
#define ATTN_SMEM (SMEM_ELEMS*2 + 512)

__global__ __launch_bounds__(256, 1) void attn_kernel(const int* __restrict__ mask)
{
    extern __shared__ __nv_bfloat16 sb[];
    unsigned char* ms = (unsigned char*)(sb + SMEM_ELEMS);

    const int tid  = threadIdx.x;
    const int lane = tid & 31, wid = tid >> 5;
    const int grp  = lane >> 2, qi = lane & 3;   // quad row-group / col-pair
    const int bh = blockIdx.y, b = bh >> 4, h = bh & 15;
    const int q0 = blockIdx.x * 128;

    const size_t bho = (size_t)bh * T_ * DK_;
    const __nv_bfloat16* gQh = g_hi + QATT + bho;
    const __nv_bfloat16* gQl = g_lo + QATT + bho;
    const __nv_bfloat16* gKh = g_hi + KATT + bho;
    const __nv_bfloat16* gKl = g_lo + KATT + bho;
    const __nv_bfloat16* gVh = g_hi + VATT + bho;
    const __nv_bfloat16* gVl = g_lo + VATT + bho;

    // stage Q (128 x 64, hi/lo)
    #pragma unroll
    for (int i = 0; i < 4; i++) {
        int id = tid + 256 * i, r = id >> 3, c8 = id & 7;
        size_t g = (size_t)(q0 + r) * DK_ + c8 * 8;
        *(uint4*)&sb[SQ_H + r * LQK + c8 * 8] = *(const uint4*)&gQh[g];
        *(uint4*)&sb[SQ_L + r * LQK + c8 * 8] = *(const uint4*)&gQl[g];
    }
    __syncthreads();

    // Q a-fragments (4 k-steps of 16 over DK=64), resident in registers
    unsigned qa_h[4][4], qa_l[4][4];
    {
        int r0 = wid * 16 + grp;
        #pragma unroll
        for (int ks = 0; ks < 4; ks++) {
            int cb = ks * 16 + qi * 2;
            qa_h[ks][0] = *(const unsigned*)&sb[SQ_H + r0 * LQK + cb];
            qa_h[ks][1] = *(const unsigned*)&sb[SQ_H + (r0 + 8) * LQK + cb];
            qa_h[ks][2] = *(const unsigned*)&sb[SQ_H + r0 * LQK + cb + 8];
            qa_h[ks][3] = *(const unsigned*)&sb[SQ_H + (r0 + 8) * LQK + cb + 8];
            qa_l[ks][0] = *(const unsigned*)&sb[SQ_L + r0 * LQK + cb];
            qa_l[ks][1] = *(const unsigned*)&sb[SQ_L + (r0 + 8) * LQK + cb];
            qa_l[ks][2] = *(const unsigned*)&sb[SQ_L + r0 * LQK + cb + 8];
            qa_l[ks][3] = *(const unsigned*)&sb[SQ_L + (r0 + 8) * LQK + cb + 8];
        }
    }

    float O[8][4];
    #pragma unroll
    for (int j = 0; j < 8; j++) O[j][0] = O[j][1] = O[j][2] = O[j][3] = 0.f;
    float mrow0 = -1e30f, mrow1 = -1e30f, lrow0 = 0.f, lrow1 = 0.f;

    for (int kt = 0; kt < 16; kt++) {
        __syncthreads();
        // stage K (rows=key, cols=d) and V transposed (rows=d, cols=key)
        #pragma unroll
        for (int i = 0; i < 4; i++) {
            int id = tid + 256 * i, r = id >> 3, c8 = id & 7;
            size_t g = (size_t)(kt * 128 + r) * DK_ + c8 * 8;
            *(uint4*)&sb[SK_H + r * LQK + c8 * 8] = *(const uint4*)&gKh[g];
            *(uint4*)&sb[SK_L + r * LQK + c8 * 8] = *(const uint4*)&gKl[g];
            uint4 vh = *(const uint4*)&gVh[g];
            uint4 vl = *(const uint4*)&gVl[g];
            const unsigned short* ph = (const unsigned short*)&vh;
            const unsigned short* pl = (const unsigned short*)&vl;
            #pragma unroll
            for (int e = 0; e < 8; e++) {
                ((unsigned short*)sb)[SV_H + (c8 * 8 + e) * LVT + r] = ph[e];
                ((unsigned short*)sb)[SV_L + (c8 * 8 + e) * LVT + r] = pl[e];
            }
        }
        if (tid < 128) ms[tid] = mask[(size_t)b * T_ + kt * 128 + tid] ? 1 : 0;
        __syncthreads();

        // ---- S = Q K^T (bf16x3) ----
        float S[16][4];
        #pragma unroll
        for (int j = 0; j < 16; j++) S[j][0] = S[j][1] = S[j][2] = S[j][3] = 0.f;

        #pragma unroll
        for (int j = 0; j < 16; j++) {
            int krow = j * 8 + grp;
            #pragma unroll
            for (int ks = 0; ks < 4; ks++) {
                int cb = ks * 16 + qi * 2;
                unsigned kb_h[2], kb_l[2];
                kb_h[0] = *(const unsigned*)&sb[SK_H + krow * LQK + cb];
                kb_h[1] = *(const unsigned*)&sb[SK_H + krow * LQK + cb + 8];
                kb_l[0] = *(const unsigned*)&sb[SK_L + krow * LQK + cb];
                kb_l[1] = *(const unsigned*)&sb[SK_L + krow * LQK + cb + 8];
                mma16816(S[j], qa_h[ks], kb_h);
                mma16816(S[j], qa_h[ks], kb_l);
                mma16816(S[j], qa_l[ks], kb_h);
            }
        }

        // ---- mask + online softmax (rows r0 = c0/c1, r0+8 = c2/c3) ----
        float ml0 = -3e38f, ml1 = -3e38f;
        #pragma unroll
        for (int j = 0; j < 16; j++) {
            if (ms[j * 8 + qi * 2])     { S[j][0] = -1e30f; S[j][2] = -1e30f; }
            if (ms[j * 8 + qi * 2 + 1]) { S[j][1] = -1e30f; S[j][3] = -1e30f; }
            ml0 = fmaxf(ml0, fmaxf(S[j][0], S[j][1]));
            ml1 = fmaxf(ml1, fmaxf(S[j][2], S[j][3]));
        }
        ml0 = fmaxf(ml0, __shfl_xor_sync(0xffffffffu, ml0, 1));
        ml0 = fmaxf(ml0, __shfl_xor_sync(0xffffffffu, ml0, 2));
        ml1 = fmaxf(ml1, __shfl_xor_sync(0xffffffffu, ml1, 1));
        ml1 = fmaxf(ml1, __shfl_xor_sync(0xffffffffu, ml1, 2));

        float mN0 = fmaxf(mrow0, ml0), mN1 = fmaxf(mrow1, ml1);
        float f0 = fexp(mrow0 - mN0), f1 = fexp(mrow1 - mN1);
        mrow0 = mN0; mrow1 = mN1;

        float ps0 = 0.f, ps1 = 0.f;
        #pragma unroll
        for (int j = 0; j < 16; j++) {
            S[j][0] = fexp(S[j][0] - mN0);
            S[j][1] = fexp(S[j][1] - mN0);
            S[j][2] = fexp(S[j][2] - mN1);
            S[j][3] = fexp(S[j][3] - mN1);
            ps0 += S[j][0] + S[j][1];
            ps1 += S[j][2] + S[j][3];
        }
        ps0 += __shfl_xor_sync(0xffffffffu, ps0, 1);
        ps0 += __shfl_xor_sync(0xffffffffu, ps0, 2);
        ps1 += __shfl_xor_sync(0xffffffffu, ps1, 1);
        ps1 += __shfl_xor_sync(0xffffffffu, ps1, 2);
        lrow0 = lrow0 * f0 + ps0;
        lrow1 = lrow1 * f1 + ps1;
        #pragma unroll
        for (int j = 0; j < 8; j++) {
            O[j][0] *= f0; O[j][1] *= f0; O[j][2] *= f1; O[j][3] *= f1;
        }

        // ---- O += P V (P from S regs, bf16x3) ----
        #pragma unroll
        for (int s = 0; s < 8; s++) {
            const float* ca = S[2 * s];
            const float* cb = S[2 * s + 1];
            unsigned pah[4], pal[4];
            pah[0] = packbf(ca[0], ca[1]);
            pah[1] = packbf(ca[2], ca[3]);
            pah[2] = packbf(cb[0], cb[1]);
            pah[3] = packbf(cb[2], cb[3]);
            pal[0] = packbf(ca[0] - lobf(pah[0]), ca[1] - hibf(pah[0]));
            pal[1] = packbf(ca[2] - lobf(pah[1]), ca[3] - hibf(pah[1]));
            pal[2] = packbf(cb[0] - lobf(pah[2]), cb[1] - hibf(pah[2]));
            pal[3] = packbf(cb[2] - lobf(pah[3]), cb[3] - hibf(pah[3]));
            #pragma unroll
            for (int j = 0; j < 8; j++) {
                int vrow = j * 8 + grp;
                int kb = s * 16 + qi * 2;
                unsigned vb_h[2], vb_l[2];
                vb_h[0] = *(const unsigned*)&sb[SV_H + vrow * LVT + kb];
                vb_h[1] = *(const unsigned*)&sb[SV_H + vrow * LVT + kb + 8];
                vb_l[0] = *(const unsigned*)&sb[SV_L + vrow * LVT + kb];
                vb_l[1] = *(const unsigned*)&sb[SV_L + vrow * LVT + kb + 8];
                mma16816(O[j], pah, vb_h);
                mma16816(O[j], pah, vb_l);
                mma16816(O[j], pal, vb_h);
            }
        }
    }

    // ---- epilogue: normalize, split to bf16 hi/lo, write AO arena ----
    float inv0 = 1.0f / lrow0, inv1 = 1.0f / lrow1;
    int r0g = q0 + wid * 16 + grp;
    __nv_bfloat16* aoh = g_hi + AOOFF;
    __nv_bfloat16* aol = g_lo + AOOFF;
    #pragma unroll
    for (int j = 0; j < 8; j++) {
        int col = h * 64 + j * 8 + qi * 2;
        float v0 = O[j][0] * inv0, v1 = O[j][1] * inv0;
        unsigned hp = packbf(v0, v1);
        unsigned lp = packbf(v0 - lobf(hp), v1 - hibf(hp));
        size_t a0 = (size_t)(r0g * B_ + b) * C_ + col;
        *(unsigned*)&aoh[a0] = hp;
        *(unsigned*)&aol[a0] = lp;
        float v2 = O[j][2] * inv1, v3 = O[j][3] * inv1;
        hp = packbf(v2, v3);
        lp = packbf(v2 - lobf(hp), v3 - hibf(hp));
        size_t a1 = (size_t)((r0g + 8) * B_ + b) * C_ + col;
        *(unsigned*)&aoh[a1] = hp;
        *(unsigned*)&aol[a1] = lp;
    }
}

// ---------------------------------------------------------------------------
extern "C" void kernel_launch(void* const* d_in, const int* in_sizes, int n_in,
                              void* d_out, int out_size)
{
    const float* query = (const float*)d_in[0];
    const float* key   = (const float*)d_in[1];
    const float* value = (const float*)d_in[2];
    const int*   mask  = (const int*)d_in[3];
    const float* Wq = (const float*)d_in[4];
    const float* bq = (const float*)d_in[5];
    const float* Wk = (const float*)d_in[6];
    const float* bk = (const float*)d_in[7];
    const float* Wv = (const float*)d_in[8];
    const float* bv = (const float*)d_in[9];
    const float* Wo = (const float*)d_in[10];
    const float* bo = (const float*)d_in[11];
    float* out = (float*)d_out;

    convert_kernel<<<(unsigned)(nX / 1024), 256>>>(query, 0 * nX, nX);
    convert_kernel<<<(unsigned)(nX / 1024), 256>>>(key,   1 * nX, nX);
    convert_kernel<<<(unsigned)(nX / 1024), 256>>>(value, 2 * nX, nX);
    convert_kernel<<<(unsigned)(nW / 1024), 256>>>(Wq, WBASE + 0 * nW, nW);
    convert_kernel<<<(unsigned)(nW / 1024), 256>>>(Wk, WBASE + 1 * nW, nW);
    convert_kernel<<<(unsigned)(nW / 1024), 256>>>(Wv, WBASE + 2 * nW, nW);
    convert_kernel<<<(unsigned)(nW / 1024), 256>>>(Wo, WBASE + 3 * nW, nW);

    cudaFuncSetAttribute(mma_gemm<0>, cudaFuncAttributeMaxDynamicSharedMemorySize, SM_GEMM_BYTES);
    cudaFuncSetAttribute(mma_gemm<1>, cudaFuncAttributeMaxDynamicSharedMemorySize, SM_GEMM_BYTES);
    cudaFuncSetAttribute(attn_kernel, cudaFuncAttributeMaxDynamicSharedMemorySize, ATTN_SMEM);

    // QKV projections -> bf16 hi/lo arenas (Q pre-scaled)
    mma_gemm<0><<<dim3(C_ / 128, M_ / 128, 3), 256, SM_GEMM_BYTES>>>(bq, bk, bv, nullptr);

    // attention on tensor cores
    attn_kernel<<<dim3(T_ / 128, B_ * H_), 256, ATTN_SMEM>>>(mask);

    // output projection
    mma_gemm<1><<<dim3(C_ / 128, M_ / 128, 1), 256, SM_GEMM_BYTES>>>(bo, nullptr, nullptr, out);
}

// round 11
// speedup vs baseline: 2.6658x; 1.1243x over previous
#include <cuda_runtime.h>
#include <cuda_bf16.h>
#include <mma.h>

using namespace nvcuda;

// Problem dims
#define T_  2048
#define B_  4
#define C_  1024
#define H_  16
#define DK_ 64
#define M_  (T_*B_)

#define nX ((size_t)M_*C_)
#define nW ((size_t)C_*C_)
#define WBASE  (3*nX)
#define AOOFF  (WBASE + 4*nW)
#define QATT   (AOOFF + nX)
#define KATT   (QATT + nX)
#define VATT   (KATT + nX)
#define ARENA  (VATT + nX)

// bf16 hi/lo arenas (allocation-free rule: device globals)
__device__ __nv_bfloat16 g_hi[ARENA];
__device__ __nv_bfloat16 g_lo[ARENA];

// ---------------------------------------------------------------------------
// helpers
// ---------------------------------------------------------------------------
__device__ __forceinline__ void mma16816(float* c, const unsigned* a, const unsigned* b) {
    asm volatile(
        "mma.sync.aligned.m16n8k16.row.col.f32.bf16.bf16.f32 "
        "{%0,%1,%2,%3}, {%4,%5,%6,%7}, {%8,%9}, {%0,%1,%2,%3};\n"
        : "+f"(c[0]), "+f"(c[1]), "+f"(c[2]), "+f"(c[3])
        : "r"(a[0]), "r"(a[1]), "r"(a[2]), "r"(a[3]), "r"(b[0]), "r"(b[1]));
}
__device__ __forceinline__ unsigned packbf(float lo, float hi) {
    unsigned r;
    asm("cvt.rn.bf16x2.f32 %0, %1, %2;" : "=r"(r) : "f"(hi), "f"(lo));
    return r;
}
__device__ __forceinline__ float lobf(unsigned u) { return __int_as_float(u << 16); }
__device__ __forceinline__ float hibf(unsigned u) { return __int_as_float(u & 0xFFFF0000u); }

__device__ __forceinline__ void cpa16(unsigned dst, const void* src) {
    asm volatile("cp.async.cg.shared.global [%0], [%1], 16;" :: "r"(dst), "l"(src));
}
__device__ __forceinline__ void cpcommit() {
    asm volatile("cp.async.commit_group;" ::: "memory");
}
template<int N> __device__ __forceinline__ void cpwait() {
    asm volatile("cp.async.wait_group %0;" :: "n"(N) : "memory");
}
__device__ __forceinline__ unsigned s2u32(const void* p) {
    return (unsigned)__cvta_generic_to_shared(p);
}

// fast exp on the FMA pipe (no MUFU): 2^(x*log2e), deg-5, ~2e-6 rel
__device__ __forceinline__ float fexp(float x) {
    x = fmaxf(x, -87.0f);
    float t  = x * 1.4426950408889634f;
    float fk = t + 12582912.0f;
    int   ki = __float_as_int(fk) - 0x4B400000;
    float r  = t - (fk - 12582912.0f);
    float p  = 1.3333558146e-3f;
    p = fmaf(p, r, 9.6181291076e-3f);
    p = fmaf(p, r, 5.5504108664e-2f);
    p = fmaf(p, r, 2.4022650696e-1f);
    p = fmaf(p, r, 6.9314718056e-1f);
    p = fmaf(p, r, 1.0f);
    return p * __int_as_float((ki + 127) << 23);
}

// ---------------------------------------------------------------------------
// fp32 -> (bf16 hi, bf16 lo) split conversion; grid.y selects source
// ---------------------------------------------------------------------------
__global__ __launch_bounds__(256) void convert_multi(
    const float* __restrict__ p0, const float* __restrict__ p1,
    const float* __restrict__ p2, const float* __restrict__ p3,
    size_t off0, size_t per, size_t n)
{
    int z = blockIdx.y;
    const float* src = (z == 0) ? p0 : (z == 1) ? p1 : (z == 2) ? p2 : p3;
    size_t off = off0 + (size_t)z * per;
    __nv_bfloat16* hp = g_hi + off;
    __nv_bfloat16* lp = g_lo + off;
    size_t i = ((size_t)blockIdx.x * blockDim.x + threadIdx.x) * 4;
    if (i >= n) return;
    float4 v = *(const float4*)(src + i);
    __nv_bfloat16 h0 = __float2bfloat16(v.x), h1 = __float2bfloat16(v.y);
    __nv_bfloat16 h2 = __float2bfloat16(v.z), h3 = __float2bfloat16(v.w);
    __nv_bfloat16 l0 = __float2bfloat16(v.x - __bfloat162float(h0));
    __nv_bfloat16 l1 = __float2bfloat16(v.y - __bfloat162float(h1));
    __nv_bfloat16 l2 = __float2bfloat16(v.z - __bfloat162float(h2));
    __nv_bfloat16 l3 = __float2bfloat16(v.w - __bfloat162float(h3));
    *(ushort4*)(hp + i) = make_ushort4(__bfloat16_as_ushort(h0), __bfloat16_as_ushort(h1),
                                       __bfloat16_as_ushort(h2), __bfloat16_as_ushort(h3));
    *(ushort4*)(lp + i) = make_ushort4(__bfloat16_as_ushort(l0), __bfloat16_as_ushort(l1),
                                       __bfloat16_as_ushort(l2), __bfloat16_as_ushort(l3));
}

// ---------------------------------------------------------------------------
// WMMA bf16x3 GEMM with cp.async double buffering.
// D[128,128] = A[128,K] * B[128,K]^T (K=1024), fp32 accum.
// smem: [Ah0 Ah1 Al0 Al1 Bh0 Bh1 Bl0 Bl1], each 128x72 bf16.
// ---------------------------------------------------------------------------
#define LDS_  72
#define BUFSZ (128 * LDS_)
#define BSBY  (BUFSZ * 2)                 // bytes per buffer
#define SM_GEMM_BYTES (8 * BSBY)          // 147456
#define LDD_  68

template<int MODE>
__global__ __launch_bounds__(256) void mma_gemm(
    const float* __restrict__ bias_q, const float* __restrict__ bias_k,
    const float* __restrict__ bias_v, float* __restrict__ Y)
{
    extern __shared__ char smc[];
    __nv_bfloat16* sbf = (__nv_bfloat16*)smc;
    float* Dst = (float*)smc;
    const unsigned smb = s2u32(smc);

    const int tid = threadIdx.x;
    const int wid = tid >> 5;
    const int wm = wid & 3, wn = wid >> 2;
    const int m0 = blockIdx.y * 128, n0 = blockIdx.x * 128;

    size_t aoff, boff;
    const float* bias;
    if (MODE == 0) {
        int z = blockIdx.z;
        aoff = (size_t)z * nX;
        boff = WBASE + (size_t)z * nW;
        bias = (z == 0) ? bias_q : (z == 1) ? bias_k : bias_v;
    } else {
        aoff = AOOFF;
        boff = WBASE + 3 * nW;
        bias = bias_q;   // bo
    }
    const __nv_bfloat16* gAh = g_hi + aoff;
    const __nv_bfloat16* gAl = g_lo + aoff;
    const __nv_bfloat16* gBh = g_hi + boff;
    const __nv_bfloat16* gBl = g_lo + boff;

    auto issue = [&](int kc, int buf) {
        #pragma unroll
        for (int t4 = 0; t4 < 4; t4++) {
            int id = tid + t4 * 256;
            int r  = id >> 3, c8 = id & 7;
            size_t ga = (size_t)(m0 + r) * C_ + kc + c8 * 8;
            size_t gb = (size_t)(n0 + r) * C_ + kc + c8 * 8;
            unsigned so = (r * LDS_ + c8 * 8) * 2;
            cpa16(smb + (0 + buf) * BSBY + so, gAh + ga);
            cpa16(smb + (2 + buf) * BSBY + so, gAl + ga);
            cpa16(smb + (4 + buf) * BSBY + so, gBh + gb);
            cpa16(smb + (6 + buf) * BSBY + so, gBl + gb);
        }
    };

    wmma::fragment<wmma::accumulator, 16, 16, 16, float> acc[2][4];
    #pragma unroll
    for (int i = 0; i < 2; i++)
        #pragma unroll
        for (int j = 0; j < 4; j++)
            wmma::fill_fragment(acc[i][j], 0.0f);

    issue(0, 0);
    cpcommit();

    for (int s = 0; s < 16; s++) {
        const int cur = s & 1;
        if (s < 15) { issue((s + 1) * 64, cur ^ 1); cpcommit(); cpwait<1>(); }
        else        { cpwait<0>(); }
        __syncthreads();

        const __nv_bfloat16* Ah = sbf + (0 + cur) * BUFSZ;
        const __nv_bfloat16* Al = sbf + (2 + cur) * BUFSZ;
        const __nv_bfloat16* Bh = sbf + (4 + cur) * BUFSZ;
        const __nv_bfloat16* Bl = sbf + (6 + cur) * BUFSZ;

        #pragma unroll
        for (int ks = 0; ks < 4; ks++) {
            int kk = ks * 16;
            wmma::fragment<wmma::matrix_a, 16, 16, 16, __nv_bfloat16, wmma::row_major> a_hi[2], a_lo[2];
            wmma::fragment<wmma::matrix_b, 16, 16, 16, __nv_bfloat16, wmma::col_major> b_hi[4], b_lo[4];
            #pragma unroll
            for (int i = 0; i < 2; i++) {
                int mrow = wm * 32 + i * 16;
                wmma::load_matrix_sync(a_hi[i], Ah + mrow * LDS_ + kk, LDS_);
                wmma::load_matrix_sync(a_lo[i], Al + mrow * LDS_ + kk, LDS_);
            }
            #pragma unroll
            for (int j = 0; j < 4; j++) {
                int ncol = wn * 64 + j * 16;
                wmma::load_matrix_sync(b_hi[j], Bh + ncol * LDS_ + kk, LDS_);
                wmma::load_matrix_sync(b_lo[j], Bl + ncol * LDS_ + kk, LDS_);
            }
            #pragma unroll
            for (int i = 0; i < 2; i++)
                #pragma unroll
                for (int j = 0; j < 4; j++) {
                    wmma::mma_sync(acc[i][j], a_hi[i], b_hi[j], acc[i][j]);
                    wmma::mma_sync(acc[i][j], a_hi[i], b_lo[j], acc[i][j]);
                    wmma::mma_sync(acc[i][j], a_lo[i], b_hi[j], acc[i][j]);
                }
        }
        __syncthreads();
    }

    // Epilogue in two 64-col halves via fp32 smem staging.
    #pragma unroll
    for (int half = 0; half < 2; half++) {
        if (wn == half) {
            #pragma unroll
            for (int i = 0; i < 2; i++)
                #pragma unroll
                for (int j = 0; j < 4; j++)
                    wmma::store_matrix_sync(
                        Dst + (wm * 32 + i * 16) * LDD_ + j * 16,
                        acc[i][j], LDD_, wmma::mem_row_major);
        }
        __syncthreads();
        #pragma unroll
        for (int t = 0; t < 32; t++) {
            int id = tid + t * 256;
            int r = id >> 6, c = id & 63;
            int m = m0 + r;
            int n = n0 + half * 64 + c;
            float v = Dst[r * LDD_ + c] + bias[n];
            if (MODE == 0) {
                int z = blockIdx.z;
                if (z == 0) v *= 0.125f;          // fold 1/sqrt(DK) into Q
                int tt = m >> 2, b = m & 3;       // m = t*B + b
                int hh = n >> 6, d = n & 63;
                __nv_bfloat16 hv = __float2bfloat16(v);
                __nv_bfloat16 lv = __float2bfloat16(v - __bfloat162float(hv));
                size_t base = (z == 0) ? QATT : (z == 1) ? KATT : VATT;
                size_t adr = base + (((size_t)(b * H_ + hh)) * T_ + tt) * DK_ + d;
                g_hi[adr] = hv;
                g_lo[adr] = lv;
            } else {
                Y[(size_t)m * C_ + n] = v;
            }
        }
        __syncthreads();
    }
}

// ---------------------------------------------------------------------------
// FA2 attention, mma.sync bf16x3, cp.async double-buffered K / V-raw tiles.
// ---------------------------------------------------------------------------
#define LQK 72
#define LVT 136
#define SQ_H   0
#define SQ_L   9216
#define SK_B   18432            // + (buf + 2*hl)*9216 : KH0 KH1 KL0 KL1
#define SVR_B  55296
#define SVT_H  92160
#define SVT_L  100864
#define SMEM_ELEMS 109568
#define ATTN_SMEM (SMEM_ELEMS * 2 + 512)

__global__ __launch_bounds__(256, 1) void attn_kernel(const int* __restrict__ mask)
{
    extern __shared__ __nv_bfloat16 sb[];
    unsigned char* ms = (unsigned char*)(sb + SMEM_ELEMS);
    const unsigned smb = s2u32(sb);

    const int tid  = threadIdx.x;
    const int lane = tid & 31, wid = tid >> 5;
    const int grp  = lane >> 2, qi = lane & 3;
    const int bh = blockIdx.y, b = bh >> 4, h = bh & 15;
    const int q0 = blockIdx.x * 128;

    const size_t bho = (size_t)bh * T_ * DK_;
    const __nv_bfloat16* gQh = g_hi + QATT + bho;
    const __nv_bfloat16* gQl = g_lo + QATT + bho;
    const __nv_bfloat16* gKh = g_hi + KATT + bho;
    const __nv_bfloat16* gKl = g_lo + KATT + bho;
    const __nv_bfloat16* gVh = g_hi + VATT + bho;
    const __nv_bfloat16* gVl = g_lo + VATT + bho;

    auto KH = [](int buf) { return SK_B + buf * 9216; };
    auto KL = [](int buf) { return SK_B + 18432 + buf * 9216; };
    auto VRH = [](int buf) { return SVR_B + buf * 9216; };
    auto VRL = [](int buf) { return SVR_B + 18432 + buf * 9216; };

    auto issueKV = [&](int kt, int buf) {
        #pragma unroll
        for (int i = 0; i < 4; i++) {
            int id = tid + 256 * i, r = id >> 3, c8 = id & 7;
            size_t g = (size_t)(kt * 128 + r) * DK_ + c8 * 8;
            unsigned so = (r * LQK + c8 * 8) * 2;
            cpa16(smb + KH(buf) * 2 + so, gKh + g);
            cpa16(smb + KL(buf) * 2 + so, gKl + g);
            cpa16(smb + VRH(buf) * 2 + so, gVh + g);
            cpa16(smb + VRL(buf) * 2 + so, gVl + g);
        }
    };

    issueKV(0, 0);
    cpcommit();

    #pragma unroll
    for (int i = 0; i < 4; i++) {
        int id = tid + 256 * i, r = id >> 3, c8 = id & 7;
        size_t g = (size_t)(q0 + r) * DK_ + c8 * 8;
        *(uint4*)&sb[SQ_H + r * LQK + c8 * 8] = *(const uint4*)&gQh[g];
        *(uint4*)&sb[SQ_L + r * LQK + c8 * 8] = *(const uint4*)&gQl[g];
    }
    __syncthreads();

    unsigned qa_h[4][4], qa_l[4][4];
    {
        int r0 = wid * 16 + grp;
        #pragma unroll
        for (int ks = 0; ks < 4; ks++) {
            int cb = ks * 16 + qi * 2;
            qa_h[ks][0] = *(const unsigned*)&sb[SQ_H + r0 * LQK + cb];
            qa_h[ks][1] = *(const unsigned*)&sb[SQ_H + (r0 + 8) * LQK + cb];
            qa_h[ks][2] = *(const unsigned*)&sb[SQ_H + r0 * LQK + cb + 8];
            qa_h[ks][3] = *(const unsigned*)&sb[SQ_H + (r0 + 8) * LQK + cb + 8];
            qa_l[ks][0] = *(const unsigned*)&sb[SQ_L + r0 * LQK + cb];
            qa_l[ks][1] = *(const unsigned*)&sb[SQ_L + (r0 + 8) * LQK + cb];
            qa_l[ks][2] = *(const unsigned*)&sb[SQ_L + r0 * LQK + cb + 8];
            qa_l[ks][3] = *(const unsigned*)&sb[SQ_L + (r0 + 8) * LQK + cb + 8];
        }
    }

    float O[8][4];
    #pragma unroll
    for (int j = 0; j < 8; j++) O[j][0] = O[j][1] = O[j][2] = O[j][3] = 0.f;
    float mrow0 = -1e30f, mrow1 = -1e30f, lrow0 = 0.f, lrow1 = 0.f;

    for (int kt = 0; kt < 16; kt++) {
        const int cur = kt & 1;
        if (kt < 15) { issueKV(kt + 1, cur ^ 1); cpcommit(); cpwait<1>(); }
        else         { cpwait<0>(); }
        __syncthreads();

        if (tid < 128) ms[tid] = mask[(size_t)b * T_ + kt * 128 + tid] ? 1 : 0;

        // ---- S = Q K^T (bf16x3) ----
        float S[16][4];
        #pragma unroll
        for (int j = 0; j < 16; j++) S[j][0] = S[j][1] = S[j][2] = S[j][3] = 0.f;
        #pragma unroll
        for (int j = 0; j < 16; j++) {
            int krow = j * 8 + grp;
            #pragma unroll
            for (int ks = 0; ks < 4; ks++) {
                int cb = ks * 16 + qi * 2;
                unsigned kb_h[2], kb_l[2];
                kb_h[0] = *(const unsigned*)&sb[KH(cur) + krow * LQK + cb];
                kb_h[1] = *(const unsigned*)&sb[KH(cur) + krow * LQK + cb + 8];
                kb_l[0] = *(const unsigned*)&sb[KL(cur) + krow * LQK + cb];
                kb_l[1] = *(const unsigned*)&sb[KL(cur) + krow * LQK + cb + 8];
                mma16816(S[j], qa_h[ks], kb_h);
                mma16816(S[j], qa_h[ks], kb_l);
                mma16816(S[j], qa_l[ks], kb_h);
            }
        }

        // ---- transpose Vraw[cur] -> VT ([d][key]) ----
        #pragma unroll
        for (int i = 0; i < 4; i++) {
            int id = tid + 256 * i, r = id >> 3, c8 = id & 7;
            uint4 vh = *(const uint4*)&sb[VRH(cur) + r * LQK + c8 * 8];
            uint4 vl = *(const uint4*)&sb[VRL(cur) + r * LQK + c8 * 8];
            const unsigned short* ph = (const unsigned short*)&vh;
            const unsigned short* pl = (const unsigned short*)&vl;
            #pragma unroll
            for (int e = 0; e < 8; e++) {
                ((unsigned short*)sb)[SVT_H + (c8 * 8 + e) * LVT + r] = ph[e];
                ((unsigned short*)sb)[SVT_L + (c8 * 8 + e) * LVT + r] = pl[e];
            }
        }
        __syncthreads();

        // ---- mask + online softmax ----
        float ml0 = -3e38f, ml1 = -3e38f;
        #pragma unroll
        for (int j = 0; j < 16; j++) {
            if (ms[j * 8 + qi * 2])     { S[j][0] = -1e30f; S[j][2] = -1e30f; }
            if (ms[j * 8 + qi * 2 + 1]) { S[j][1] = -1e30f; S[j][3] = -1e30f; }
            ml0 = fmaxf(ml0, fmaxf(S[j][0], S[j][1]));
            ml1 = fmaxf(ml1, fmaxf(S[j][2], S[j][3]));
        }
        ml0 = fmaxf(ml0, __shfl_xor_sync(0xffffffffu, ml0, 1));
        ml0 = fmaxf(ml0, __shfl_xor_sync(0xffffffffu, ml0, 2));
        ml1 = fmaxf(ml1, __shfl_xor_sync(0xffffffffu, ml1, 1));
        ml1 = fmaxf(ml1, __shfl_xor_sync(0xffffffffu, ml1, 2));

        float mN0 = fmaxf(mrow0, ml0), mN1 = fmaxf(mrow1, ml1);
        float f0 = fexp(mrow0 - mN0), f1 = fexp(mrow1 - mN1);
        mrow0 = mN0; mrow1 = mN1;

        float ps0 = 0.f, ps1 = 0.f;
        #pragma unroll
        for (int j = 0; j < 16; j++) {
            S[j][0] = fexp(S[j][0] - mN0);
            S[j][1] = fexp(S[j][1] - mN0);
            S[j][2] = fexp(S[j][2] - mN1);
            S[j][3] = fexp(S[j][3] - mN1);
            ps0 += S[j][0] + S[j][1];
            ps1 += S[j][2] + S[j][3];
        }
        ps0 += __shfl_xor_sync(0xffffffffu, ps0, 1);
        ps0 += __shfl_xor_sync(0xffffffffu, ps0, 2);
        ps1 += __shfl_xor_sync(0xffffffffu, ps1, 1);
        ps1 += __shfl_xor_sync(0xffffffffu, ps1, 2);
        lrow0 = lrow0 * f0 + ps0;
        lrow1 = lrow1 * f1 + ps1;
        #pragma unroll
        for (int j = 0; j < 8; j++) {
            O[j][0] *= f0; O[j][1] *= f0; O[j][2] *= f1; O[j][3] *= f1;
        }

        // ---- O += P V ----
        #pragma unroll
        for (int s = 0; s < 8; s++) {
            const float* ca = S[2 * s];
            const float* cb = S[2 * s + 1];
            unsigned pah[4], pal[4];
            pah[0] = packbf(ca[0], ca[1]);
            pah[1] = packbf(ca[2], ca[3]);
            pah[2] = packbf(cb[0], cb[1]);
            pah[3] = packbf(cb[2], cb[3]);
            pal[0] = packbf(ca[0] - lobf(pah[0]), ca[1] - hibf(pah[0]));
            pal[1] = packbf(ca[2] - lobf(pah[1]), ca[3] - hibf(pah[1]));
            pal[2] = packbf(cb[0] - lobf(pah[2]), cb[1] - hibf(pah[2]));
            pal[3] = packbf(cb[2] - lobf(pah[3]), cb[3] - hibf(pah[3]));
            #pragma unroll
            for (int j = 0; j < 8; j++) {
                int vrow = j * 8 + grp;
                int kb = s * 16 + qi * 2;
                unsigned vb_h[2], vb_l[2];
                vb_h[0] = *(const unsigned*)&sb[SVT_H + vrow * LVT + kb];
                vb_h[1] = *(const unsigned*)&sb[SVT_H + vrow * LVT + kb + 8];
                vb_l[0] = *(const unsigned*)&sb[SVT_L + vrow * LVT + kb];
                vb_l[1] = *(const unsigned*)&sb[SVT_L + vrow * LVT + kb + 8];
                mma16816(O[j], pah, vb_h);
                mma16816(O[j], pah, vb_l);
                mma16816(O[j], pal, vb_h);
            }
        }
    }

    // ---- epilogue ----
    float inv0 = 1.0f / lrow0, inv1 = 1.0f / lrow1;
    int r0g = q0 + wid * 16 + grp;
    __nv_bfloat16* aoh = g_hi + AOOFF;
    __nv_bfloat16* aol = g_lo + AOOFF;
    #pragma unroll
    for (int j = 0; j < 8; j++) {
        int col = h * 64 + j * 8 + qi * 2;
        float v0 = O[j][0] * inv0, v1 = O[j][1] * inv0;
        unsigned hp = packbf(v0, v1);
        unsigned lp = packbf(v0 - lobf(hp), v1 - hibf(hp));
        size_t a0 = (size_t)(r0g * B_ + b) * C_ + col;
        *(unsigned*)&aoh[a0] = hp;
        *(unsigned*)&aol[a0] = lp;
        float v2 = O[j][2] * inv1, v3 = O[j][3] * inv1;
        hp = packbf(v2, v3);
        lp = packbf(v2 - lobf(hp), v3 - hibf(hp));
        size_t a1 = (size_t)((r0g + 8) * B_ + b) * C_ + col;
        *(unsigned*)&aoh[a1] = hp;
        *(unsigned*)&aol[a1] = lp;
    }
}

// ---------------------------------------------------------------------------
extern "C" void kernel_launch(void* const* d_in, const int* in_sizes, int n_in,
                              void* d_out, int out_size)
{
    const float* query = (const float*)d_in[0];
    const float* key   = (const float*)d_in[1];
    const float* value = (const float*)d_in[2];
    const int*   mask  = (const int*)d_in[3];
    const float* Wq = (const float*)d_in[4];
    const float* bq = (const float*)d_in[5];
    const float* Wk = (const float*)d_in[6];
    const float* bk = (const float*)d_in[7];
    const float* Wv = (const float*)d_in[8];
    const float* bv = (const float*)d_in[9];
    const float* Wo = (const float*)d_in[10];
    const float* bo = (const float*)d_in[11];
    float* out = (float*)d_out;

    convert_multi<<<dim3((unsigned)(nX / 1024), 3), 256>>>(
        query, key, value, nullptr, 0, nX, nX);
    convert_multi<<<dim3((unsigned)(nW / 1024), 4), 256>>>(
        Wq, Wk, Wv, Wo, WBASE, nW, nW);

    cudaFuncSetAttribute(mma_gemm<0>, cudaFuncAttributeMaxDynamicSharedMemorySize, SM_GEMM_BYTES);
    cudaFuncSetAttribute(mma_gemm<1>, cudaFuncAttributeMaxDynamicSharedMemorySize, SM_GEMM_BYTES);
    cudaFuncSetAttribute(attn_kernel, cudaFuncAttributeMaxDynamicSharedMemorySize, ATTN_SMEM);

    mma_gemm<0><<<dim3(C_ / 128, M_ / 128, 3), 256, SM_GEMM_BYTES>>>(bq, bk, bv, nullptr);
    attn_kernel<<<dim3(T_ / 128, B_ * H_), 256, ATTN_SMEM>>>(mask);
    mma_gemm<1><<<dim3(C_ / 128, M_ / 128, 1), 256, SM_GEMM_BYTES>>>(bo, nullptr, nullptr, out);
}

// round 14
// speedup vs baseline: 3.0303x; 1.1367x over previous
#include <cuda_runtime.h>
#include <cuda_bf16.h>
#include <mma.h>

using namespace nvcuda;

// Problem dims
#define T_  2048
#define B_  4
#define C_  1024
#define H_  16
#define DK_ 64
#define M_  (T_*B_)

#define nX ((size_t)M_*C_)
#define nW ((size_t)C_*C_)
#define WBASE  (3*nX)
#define AOOFF  (WBASE + 4*nW)
#define QATT   (AOOFF + nX)
#define KATT   (QATT + nX)
#define VATT   (KATT + nX)
#define ARENA  (VATT + nX)

// bf16 hi/lo arenas (allocation-free rule: device globals)
__device__ __nv_bfloat16 g_hi[ARENA];
__device__ __nv_bfloat16 g_lo[ARENA];

// ---------------------------------------------------------------------------
// helpers
// ---------------------------------------------------------------------------
__device__ __forceinline__ void mma16816(float* c, const unsigned* a, const unsigned* b) {
    asm volatile(
        "mma.sync.aligned.m16n8k16.row.col.f32.bf16.bf16.f32 "
        "{%0,%1,%2,%3}, {%4,%5,%6,%7}, {%8,%9}, {%0,%1,%2,%3};\n"
        : "+f"(c[0]), "+f"(c[1]), "+f"(c[2]), "+f"(c[3])
        : "r"(a[0]), "r"(a[1]), "r"(a[2]), "r"(a[3]), "r"(b[0]), "r"(b[1]));
}
__device__ __forceinline__ void ldm4(unsigned* r, unsigned addr) {
    asm volatile("ldmatrix.sync.aligned.m8n8.x4.shared.b16 {%0,%1,%2,%3}, [%4];"
        : "=r"(r[0]), "=r"(r[1]), "=r"(r[2]), "=r"(r[3]) : "r"(addr));
}
__device__ __forceinline__ void ldm4t(unsigned* r, unsigned addr) {
    asm volatile("ldmatrix.sync.aligned.m8n8.x4.trans.shared.b16 {%0,%1,%2,%3}, [%4];"
        : "=r"(r[0]), "=r"(r[1]), "=r"(r[2]), "=r"(r[3]) : "r"(addr));
}
__device__ __forceinline__ unsigned packbf(float lo, float hi) {
    unsigned r;
    asm("cvt.rn.bf16x2.f32 %0, %1, %2;" : "=r"(r) : "f"(hi), "f"(lo));
    return r;
}
__device__ __forceinline__ float lobf(unsigned u) { return __int_as_float(u << 16); }
__device__ __forceinline__ float hibf(unsigned u) { return __int_as_float(u & 0xFFFF0000u); }

__device__ __forceinline__ void cpa16(unsigned dst, const void* src) {
    asm volatile("cp.async.cg.shared.global [%0], [%1], 16;" :: "r"(dst), "l"(src));
}
__device__ __forceinline__ void cpcommit() {
    asm volatile("cp.async.commit_group;" ::: "memory");
}
template<int N> __device__ __forceinline__ void cpwait() {
    asm volatile("cp.async.wait_group %0;" :: "n"(N) : "memory");
}
__device__ __forceinline__ unsigned s2u32(const void* p) {
    return (unsigned)__cvta_generic_to_shared(p);
}

// fast exp on the FMA pipe (no MUFU): 2^(x*log2e), deg-5, ~2e-6 rel
__device__ __forceinline__ float fexp(float x) {
    x = fmaxf(x, -87.0f);
    float t  = x * 1.4426950408889634f;
    float fk = t + 12582912.0f;
    int   ki = __float_as_int(fk) - 0x4B400000;
    float r  = t - (fk - 12582912.0f);
    float p  = 1.3333558146e-3f;
    p = fmaf(p, r, 9.6181291076e-3f);
    p = fmaf(p, r, 5.5504108664e-2f);
    p = fmaf(p, r, 2.4022650696e-1f);
    p = fmaf(p, r, 6.9314718056e-1f);
    p = fmaf(p, r, 1.0f);
    return p * __int_as_float((ki + 127) << 23);
}

// ---------------------------------------------------------------------------
// fp32 -> (bf16 hi, bf16 lo) split conversion; grid.y selects source
// ---------------------------------------------------------------------------
__global__ __launch_bounds__(256) void convert_multi(
    const float* __restrict__ p0, const float* __restrict__ p1,
    const float* __restrict__ p2, const float* __restrict__ p3,
    size_t off0, size_t per, size_t n)
{
    int z = blockIdx.y;
    const float* src = (z == 0) ? p0 : (z == 1) ? p1 : (z == 2) ? p2 : p3;
    size_t off = off0 + (size_t)z * per;
    __nv_bfloat16* hp = g_hi + off;
    __nv_bfloat16* lp = g_lo + off;
    size_t i = ((size_t)blockIdx.x * blockDim.x + threadIdx.x) * 4;
    if (i >= n) return;
    float4 v = *(const float4*)(src + i);
    __nv_bfloat16 h0 = __float2bfloat16(v.x), h1 = __float2bfloat16(v.y);
    __nv_bfloat16 h2 = __float2bfloat16(v.z), h3 = __float2bfloat16(v.w);
    __nv_bfloat16 l0 = __float2bfloat16(v.x - __bfloat162float(h0));
    __nv_bfloat16 l1 = __float2bfloat16(v.y - __bfloat162float(h1));
    __nv_bfloat16 l2 = __float2bfloat16(v.z - __bfloat162float(h2));
    __nv_bfloat16 l3 = __float2bfloat16(v.w - __bfloat162float(h3));
    *(ushort4*)(hp + i) = make_ushort4(__bfloat16_as_ushort(h0), __bfloat16_as_ushort(h1),
                                       __bfloat16_as_ushort(h2), __bfloat16_as_ushort(h3));
    *(ushort4*)(lp + i) = make_ushort4(__bfloat16_as_ushort(l0), __bfloat16_as_ushort(l1),
                                       __bfloat16_as_ushort(l2), __bfloat16_as_ushort(l3));
}

// ---------------------------------------------------------------------------
// WMMA bf16x3 GEMM, cp.async double-buffered, one barrier per k-chunk.
// D[128,128] = A[128,K] * B[128,K]^T (K=1024), fp32 accum.
// ---------------------------------------------------------------------------
#define LDS_  72
#define BUFSZ (128 * LDS_)
#define BSBY  (BUFSZ * 2)
#define SM_GEMM_BYTES (8 * BSBY)          // 147456
#define LDD_  68

template<int MODE>
__global__ __launch_bounds__(256) void mma_gemm(
    const float* __restrict__ bias_q, const float* __restrict__ bias_k,
    const float* __restrict__ bias_v, float* __restrict__ Y)
{
    extern __shared__ char smc[];
    __nv_bfloat16* sbf = (__nv_bfloat16*)smc;
    float* Dst = (float*)smc;
    const unsigned smb = s2u32(smc);

    const int tid = threadIdx.x;
    const int wid = tid >> 5;
    const int wm = wid & 3, wn = wid >> 2;
    const int m0 = blockIdx.y * 128, n0 = blockIdx.x * 128;

    size_t aoff, boff;
    const float* bias;
    if (MODE == 0) {
        int z = blockIdx.z;
        aoff = (size_t)z * nX;
        boff = WBASE + (size_t)z * nW;
        bias = (z == 0) ? bias_q : (z == 1) ? bias_k : bias_v;
    } else {
        aoff = AOOFF;
        boff = WBASE + 3 * nW;
        bias = bias_q;   // bo
    }
    const __nv_bfloat16* gAh = g_hi + aoff;
    const __nv_bfloat16* gAl = g_lo + aoff;
    const __nv_bfloat16* gBh = g_hi + boff;
    const __nv_bfloat16* gBl = g_lo + boff;

    auto issue = [&](int kc, int buf) {
        #pragma unroll
        for (int t4 = 0; t4 < 4; t4++) {
            int id = tid + t4 * 256;
            int r  = id >> 3, c8 = id & 7;
            size_t ga = (size_t)(m0 + r) * C_ + kc + c8 * 8;
            size_t gb = (size_t)(n0 + r) * C_ + kc + c8 * 8;
            unsigned so = (r * LDS_ + c8 * 8) * 2;
            cpa16(smb + (0 + buf) * BSBY + so, gAh + ga);
            cpa16(smb + (2 + buf) * BSBY + so, gAl + ga);
            cpa16(smb + (4 + buf) * BSBY + so, gBh + gb);
            cpa16(smb + (6 + buf) * BSBY + so, gBl + gb);
        }
    };

    wmma::fragment<wmma::accumulator, 16, 16, 16, float> acc[2][4];
    #pragma unroll
    for (int i = 0; i < 2; i++)
        #pragma unroll
        for (int j = 0; j < 4; j++)
            wmma::fill_fragment(acc[i][j], 0.0f);

    issue(0, 0);
    cpcommit();

    for (int s = 0; s < 16; s++) {
        const int cur = s & 1;
        cpwait<0>();
        __syncthreads();                 // data[cur] visible; prior reads of cur^1 done
        if (s < 15) { issue((s + 1) * 64, cur ^ 1); cpcommit(); }

        const __nv_bfloat16* Ah = sbf + (0 + cur) * BUFSZ;
        const __nv_bfloat16* Al = sbf + (2 + cur) * BUFSZ;
        const __nv_bfloat16* Bh = sbf + (4 + cur) * BUFSZ;
        const __nv_bfloat16* Bl = sbf + (6 + cur) * BUFSZ;

        #pragma unroll
        for (int ks = 0; ks < 4; ks++) {
            int kk = ks * 16;
            wmma::fragment<wmma::matrix_a, 16, 16, 16, __nv_bfloat16, wmma::row_major> a_hi[2], a_lo[2];
            wmma::fragment<wmma::matrix_b, 16, 16, 16, __nv_bfloat16, wmma::col_major> b_hi[4], b_lo[4];
            #pragma unroll
            for (int i = 0; i < 2; i++) {
                int mrow = wm * 32 + i * 16;
                wmma::load_matrix_sync(a_hi[i], Ah + mrow * LDS_ + kk, LDS_);
                wmma::load_matrix_sync(a_lo[i], Al + mrow * LDS_ + kk, LDS_);
            }
            #pragma unroll
            for (int j = 0; j < 4; j++) {
                int ncol = wn * 64 + j * 16;
                wmma::load_matrix_sync(b_hi[j], Bh + ncol * LDS_ + kk, LDS_);
                wmma::load_matrix_sync(b_lo[j], Bl + ncol * LDS_ + kk, LDS_);
            }
            #pragma unroll
            for (int i = 0; i < 2; i++)
                #pragma unroll
                for (int j = 0; j < 4; j++) {
                    wmma::mma_sync(acc[i][j], a_hi[i], b_hi[j], acc[i][j]);
                    wmma::mma_sync(acc[i][j], a_hi[i], b_lo[j], acc[i][j]);
                    wmma::mma_sync(acc[i][j], a_lo[i], b_hi[j], acc[i][j]);
                }
        }
    }
    __syncthreads();                     // all compute done before Dst aliases buffers

    // Epilogue in two 64-col halves via fp32 smem staging.
    #pragma unroll
    for (int half = 0; half < 2; half++) {
        if (wn == half) {
            #pragma unroll
            for (int i = 0; i < 2; i++)
                #pragma unroll
                for (int j = 0; j < 4; j++)
                    wmma::store_matrix_sync(
                        Dst + (wm * 32 + i * 16) * LDD_ + j * 16,
                        acc[i][j], LDD_, wmma::mem_row_major);
        }
        __syncthreads();
        #pragma unroll
        for (int t = 0; t < 32; t++) {
            int id = tid + t * 256;
            int r = id >> 6, c = id & 63;
            int m = m0 + r;
            int n = n0 + half * 64 + c;
            float v = Dst[r * LDD_ + c] + bias[n];
            if (MODE == 0) {
                int z = blockIdx.z;
                if (z == 0) v *= 0.125f;          // fold 1/sqrt(DK) into Q
                int tt = m >> 2, b = m & 3;       // m = t*B + b
                int hh = n >> 6, d = n & 63;
                __nv_bfloat16 hv = __float2bfloat16(v);
                __nv_bfloat16 lv = __float2bfloat16(v - __bfloat162float(hv));
                size_t base = (z == 0) ? QATT : (z == 1) ? KATT : VATT;
                size_t adr = base + (((size_t)(b * H_ + hh)) * T_ + tt) * DK_ + d;
                g_hi[adr] = hv;
                g_lo[adr] = lv;
            } else {
                Y[(size_t)m * C_ + n] = v;
            }
        }
        __syncthreads();
    }
}

// ---------------------------------------------------------------------------
// FA2 attention: mma.sync bf16x3, cp.async double-buffered K/V, ldmatrix
// fragment loads (V via .trans — no smem transpose), one barrier per tile.
// ---------------------------------------------------------------------------
#define LQK 72
#define SQ_H   0
#define SQ_L   9216
#define SMEM_ELEMS 92160
#define ATTN_SMEM (SMEM_ELEMS * 2 + 512)

__global__ __launch_bounds__(256, 1) void attn_kernel(const int* __restrict__ mask)
{
    extern __shared__ __nv_bfloat16 sb[];
    unsigned char* ms = (unsigned char*)(sb + SMEM_ELEMS);   // 2 x 128
    const unsigned smb = s2u32(sb);

    const int tid  = threadIdx.x;
    const int lane = tid & 31, wid = tid >> 5;
    const int grp  = lane >> 2, qi = lane & 3;
    const int lrow = lane & 7, lmat = lane >> 3;             // ldmatrix lane roles
    const int bh = blockIdx.y, b = bh >> 4, h = bh & 15;
    const int q0 = blockIdx.x * 128;

    const size_t bho = (size_t)bh * T_ * DK_;
    const __nv_bfloat16* gQh = g_hi + QATT + bho;
    const __nv_bfloat16* gQl = g_lo + QATT + bho;
    const __nv_bfloat16* gKh = g_hi + KATT + bho;
    const __nv_bfloat16* gKl = g_lo + KATT + bho;
    const __nv_bfloat16* gVh = g_hi + VATT + bho;
    const __nv_bfloat16* gVl = g_lo + VATT + bho;

    auto KH = [](int buf) { return 18432 + buf * 9216; };
    auto KL = [](int buf) { return 36864 + buf * 9216; };
    auto VH = [](int buf) { return 55296 + buf * 9216; };
    auto VL = [](int buf) { return 73728 + buf * 9216; };

    auto issueKV = [&](int kt, int buf) {
        #pragma unroll
        for (int i = 0; i < 4; i++) {
            int id = tid + 256 * i, r = id >> 3, c8 = id & 7;
            size_t g = (size_t)(kt * 128 + r) * DK_ + c8 * 8;
            unsigned so = (r * LQK + c8 * 8) * 2;
            cpa16(smb + KH(buf) * 2 + so, gKh + g);
            cpa16(smb + KL(buf) * 2 + so, gKl + g);
            cpa16(smb + VH(buf) * 2 + so, gVh + g);
            cpa16(smb + VL(buf) * 2 + so, gVl + g);
        }
    };

    issueKV(0, 0);
    cpcommit();

    // stage Q while tile-0 copies fly
    #pragma unroll
    for (int i = 0; i < 4; i++) {
        int id = tid + 256 * i, r = id >> 3, c8 = id & 7;
        size_t g = (size_t)(q0 + r) * DK_ + c8 * 8;
        *(uint4*)&sb[SQ_H + r * LQK + c8 * 8] = *(const uint4*)&gQh[g];
        *(uint4*)&sb[SQ_L + r * LQK + c8 * 8] = *(const uint4*)&gQl[g];
    }
    if (tid < 128) ms[tid] = mask[(size_t)b * T_ + tid] ? 1 : 0;   // tile 0 mask -> ms[0]
    __syncthreads();

    unsigned qa_h[4][4], qa_l[4][4];
    {
        int r0 = wid * 16 + grp;
        #pragma unroll
        for (int ks = 0; ks < 4; ks++) {
            int cb = ks * 16 + qi * 2;
            qa_h[ks][0] = *(const unsigned*)&sb[SQ_H + r0 * LQK + cb];
            qa_h[ks][1] = *(const unsigned*)&sb[SQ_H + (r0 + 8) * LQK + cb];
            qa_h[ks][2] = *(const unsigned*)&sb[SQ_H + r0 * LQK + cb + 8];
            qa_h[ks][3] = *(const unsigned*)&sb[SQ_H + (r0 + 8) * LQK + cb + 8];
            qa_l[ks][0] = *(const unsigned*)&sb[SQ_L + r0 * LQK + cb];
            qa_l[ks][1] = *(const unsigned*)&sb[SQ_L + (r0 + 8) * LQK + cb];
            qa_l[ks][2] = *(const unsigned*)&sb[SQ_L + r0 * LQK + cb + 8];
            qa_l[ks][3] = *(const unsigned*)&sb[SQ_L + (r0 + 8) * LQK + cb + 8];
        }
    }

    float O[8][4];
    #pragma unroll
    for (int j = 0; j < 8; j++) O[j][0] = O[j][1] = O[j][2] = O[j][3] = 0.f;
    float mrow0 = -1e30f, mrow1 = -1e30f, lrow0 = 0.f, lrow1 = 0.f;

    for (int kt = 0; kt < 16; kt++) {
        const int cur = kt & 1;
        cpwait<0>();
        __syncthreads();     // tile-cur data + ms[cur] visible; prior reads of cur^1 done

        if (kt < 15) {
            issueKV(kt + 1, cur ^ 1);
            cpcommit();
            if (tid < 128)
                ms[(cur ^ 1) * 128 + tid] = mask[(size_t)b * T_ + (kt + 1) * 128 + tid] ? 1 : 0;
        }
        const unsigned char* mcur = ms + cur * 128;

        // ---- S = Q K^T (bf16x3), K fragments via ldmatrix.x4 ----
        float S[16][4];
        #pragma unroll
        for (int j = 0; j < 16; j++) S[j][0] = S[j][1] = S[j][2] = S[j][3] = 0.f;
        #pragma unroll
        for (int j = 0; j < 16; j++) {
            unsigned kbh[8], kbl[8];   // [ks*2 + reg]
            unsigned ah = smb + (KH(cur) + (j * 8 + lrow) * LQK + lmat * 8) * 2;
            unsigned al = smb + (KL(cur) + (j * 8 + lrow) * LQK + lmat * 8) * 2;
            ldm4(kbh,     ah);         // d 0..31  -> ks0,ks1
            ldm4(kbh + 4, ah + 64);    // d 32..63 -> ks2,ks3
            ldm4(kbl,     al);
            ldm4(kbl + 4, al + 64);
            #pragma unroll
            for (int ks = 0; ks < 4; ks++) {
                mma16816(S[j], qa_h[ks], kbh + ks * 2);
                mma16816(S[j], qa_h[ks], kbl + ks * 2);
                mma16816(S[j], qa_l[ks], kbh + ks * 2);
            }
        }

        // ---- mask + online softmax ----
        float ml0 = -3e38f, ml1 = -3e38f;
        #pragma unroll
        for (int j = 0; j < 16; j++) {
            if (mcur[j * 8 + qi * 2])     { S[j][0] = -1e30f; S[j][2] = -1e30f; }
            if (mcur[j * 8 + qi * 2 + 1]) { S[j][1] = -1e30f; S[j][3] = -1e30f; }
            ml0 = fmaxf(ml0, fmaxf(S[j][0], S[j][1]));
            ml1 = fmaxf(ml1, fmaxf(S[j][2], S[j][3]));
        }
        ml0 = fmaxf(ml0, __shfl_xor_sync(0xffffffffu, ml0, 1));
        ml0 = fmaxf(ml0, __shfl_xor_sync(0xffffffffu, ml0, 2));
        ml1 = fmaxf(ml1, __shfl_xor_sync(0xffffffffu, ml1, 1));
        ml1 = fmaxf(ml1, __shfl_xor_sync(0xffffffffu, ml1, 2));

        float mN0 = fmaxf(mrow0, ml0), mN1 = fmaxf(mrow1, ml1);
        float f0 = fexp(mrow0 - mN0), f1 = fexp(mrow1 - mN1);
        mrow0 = mN0; mrow1 = mN1;

        float ps0 = 0.f, ps1 = 0.f;
        #pragma unroll
        for (int j = 0; j < 16; j++) {
            S[j][0] = fexp(S[j][0] - mN0);
            S[j][1] = fexp(S[j][1] - mN0);
            S[j][2] = fexp(S[j][2] - mN1);
            S[j][3] = fexp(S[j][3] - mN1);
            ps0 += S[j][0] + S[j][1];
            ps1 += S[j][2] + S[j][3];
        }
        ps0 += __shfl_xor_sync(0xffffffffu, ps0, 1);
        ps0 += __shfl_xor_sync(0xffffffffu, ps0, 2);
        ps1 += __shfl_xor_sync(0xffffffffu, ps1, 1);
        ps1 += __shfl_xor_sync(0xffffffffu, ps1, 2);
        lrow0 = lrow0 * f0 + ps0;
        lrow1 = lrow1 * f1 + ps1;
        #pragma unroll
        for (int j = 0; j < 8; j++) {
            O[j][0] *= f0; O[j][1] *= f0; O[j][2] *= f1; O[j][3] *= f1;
        }

        // ---- O += P V; V fragments via ldmatrix.x4.trans (no transpose pass) ----
        #pragma unroll
        for (int s = 0; s < 8; s++) {
            const float* ca = S[2 * s];
            const float* cb = S[2 * s + 1];
            unsigned pah[4], pal[4];
            pah[0] = packbf(ca[0], ca[1]);
            pah[1] = packbf(ca[2], ca[3]);
            pah[2] = packbf(cb[0], cb[1]);
            pah[3] = packbf(cb[2], cb[3]);
            pal[0] = packbf(ca[0] - lobf(pah[0]), ca[1] - hibf(pah[0]));
            pal[1] = packbf(ca[2] - lobf(pah[1]), ca[3] - hibf(pah[1]));
            pal[2] = packbf(cb[0] - lobf(pah[2]), cb[1] - hibf(pah[2]));
            pal[3] = packbf(cb[2] - lobf(pah[3]), cb[3] - hibf(pah[3]));

            unsigned vbh[16], vbl[16];  // [j*2 + reg], j = d-block 0..7
            #pragma unroll
            for (int jp = 0; jp < 4; jp++) {
                unsigned av = smb + (VH(cur) + (s * 16 + (lmat & 1) * 8 + lrow) * LQK
                                    + (jp * 2 + (lmat >> 1)) * 8) * 2;
                unsigned al = smb + (VL(cur) + (s * 16 + (lmat & 1) * 8 + lrow) * LQK
                                    + (jp * 2 + (lmat >> 1)) * 8) * 2;
                ldm4t(vbh + jp * 4, av);
                ldm4t(vbl + jp * 4, al);
            }
            #pragma unroll
            for (int j = 0; j < 8; j++) {
                mma16816(O[j], pah, vbh + j * 2);
                mma16816(O[j], pah, vbl + j * 2);
                mma16816(O[j], pal, vbh + j * 2);
            }
        }
    }

    // ---- epilogue ----
    float inv0 = 1.0f / lrow0, inv1 = 1.0f / lrow1;
    int r0g = q0 + wid * 16 + grp;
    __nv_bfloat16* aoh = g_hi + AOOFF;
    __nv_bfloat16* aol = g_lo + AOOFF;
    #pragma unroll
    for (int j = 0; j < 8; j++) {
        int col = h * 64 + j * 8 + qi * 2;
        float v0 = O[j][0] * inv0, v1 = O[j][1] * inv0;
        unsigned hp = packbf(v0, v1);
        unsigned lp = packbf(v0 - lobf(hp), v1 - hibf(hp));
        size_t a0 = (size_t)(r0g * B_ + b) * C_ + col;
        *(unsigned*)&aoh[a0] = hp;
        *(unsigned*)&aol[a0] = lp;
        float v2 = O[j][2] * inv1, v3 = O[j][3] * inv1;
        hp = packbf(v2, v3);
        lp = packbf(v2 - lobf(hp), v3 - hibf(hp));
        size_t a1 = (size_t)((r0g + 8) * B_ + b) * C_ + col;
        *(unsigned*)&aoh[a1] = hp;
        *(unsigned*)&aol[a1] = lp;
    }
}

// ---------------------------------------------------------------------------
extern "C" void kernel_launch(void* const* d_in, const int* in_sizes, int n_in,
                              void* d_out, int out_size)
{
    const float* query = (const float*)d_in[0];
    const float* key   = (const float*)d_in[1];
    const float* value = (const float*)d_in[2];
    const int*   mask  = (const int*)d_in[3];
    const float* Wq = (const float*)d_in[4];
    const float* bq = (const float*)d_in[5];
    const float* Wk = (const float*)d_in[6];
    const float* bk = (const float*)d_in[7];
    const float* Wv = (const float*)d_in[8];
    const float* bv = (const float*)d_in[9];
    const float* Wo = (const float*)d_in[10];
    const float* bo = (const float*)d_in[11];
    float* out = (float*)d_out;

    convert_multi<<<dim3((unsigned)(nX / 1024), 3), 256>>>(
        query, key, value, nullptr, 0, nX, nX);
    convert_multi<<<dim3((unsigned)(nW / 1024), 4), 256>>>(
        Wq, Wk, Wv, Wo, WBASE, nW, nW);

    cudaFuncSetAttribute(mma_gemm<0>, cudaFuncAttributeMaxDynamicSharedMemorySize, SM_GEMM_BYTES);
    cudaFuncSetAttribute(mma_gemm<1>, cudaFuncAttributeMaxDynamicSharedMemorySize, SM_GEMM_BYTES);
    cudaFuncSetAttribute(attn_kernel, cudaFuncAttributeMaxDynamicSharedMemorySize, ATTN_SMEM);

    mma_gemm<0><<<dim3(C_ / 128, M_ / 128, 3), 256, SM_GEMM_BYTES>>>(bq, bk, bv, nullptr);
    attn_kernel<<<dim3(T_ / 128, B_ * H_), 256, ATTN_SMEM>>>(mask);
    mma_gemm<1><<<dim3(C_ / 128, M_ / 128, 1), 256, SM_GEMM_BYTES>>>(bo, nullptr, nullptr, out);
}

// round 15
// speedup vs baseline: 3.0479x; 1.0058x over previous
#include <cuda_runtime.h>
#include <cuda_bf16.h>
#include <mma.h>

using namespace nvcuda;

// Problem dims
#define T_  2048
#define B_  4
#define C_  1024
#define H_  16
#define DK_ 64
#define M_  (T_*B_)

#define nX ((size_t)M_*C_)
#define nW ((size_t)C_*C_)
#define WBASE  (3*nX)
#define AOOFF  (WBASE + 4*nW)
#define QATT   (AOOFF + nX)
#define KATT   (QATT + nX)
#define VATT   (KATT + nX)
#define ARENA  (VATT + nX)

// bf16 hi/lo arenas (allocation-free rule: device globals)
__device__ __nv_bfloat16 g_hi[ARENA];
__device__ __nv_bfloat16 g_lo[ARENA];

// ---------------------------------------------------------------------------
// helpers
// ---------------------------------------------------------------------------
__device__ __forceinline__ void mma16816(float* c, const unsigned* a, const unsigned* b) {
    asm volatile(
        "mma.sync.aligned.m16n8k16.row.col.f32.bf16.bf16.f32 "
        "{%0,%1,%2,%3}, {%4,%5,%6,%7}, {%8,%9}, {%0,%1,%2,%3};\n"
        : "+f"(c[0]), "+f"(c[1]), "+f"(c[2]), "+f"(c[3])
        : "r"(a[0]), "r"(a[1]), "r"(a[2]), "r"(a[3]), "r"(b[0]), "r"(b[1]));
}
__device__ __forceinline__ void ldm4(unsigned* r, unsigned addr) {
    asm volatile("ldmatrix.sync.aligned.m8n8.x4.shared.b16 {%0,%1,%2,%3}, [%4];"
        : "=r"(r[0]), "=r"(r[1]), "=r"(r[2]), "=r"(r[3]) : "r"(addr));
}
__device__ __forceinline__ void ldm4t(unsigned* r, unsigned addr) {
    asm volatile("ldmatrix.sync.aligned.m8n8.x4.trans.shared.b16 {%0,%1,%2,%3}, [%4];"
        : "=r"(r[0]), "=r"(r[1]), "=r"(r[2]), "=r"(r[3]) : "r"(addr));
}
__device__ __forceinline__ unsigned packbf(float lo, float hi) {
    unsigned r;
    asm("cvt.rn.bf16x2.f32 %0, %1, %2;" : "=r"(r) : "f"(hi), "f"(lo));
    return r;
}
__device__ __forceinline__ float lobf(unsigned u) { return __int_as_float(u << 16); }
__device__ __forceinline__ float hibf(unsigned u) { return __int_as_float(u & 0xFFFF0000u); }

__device__ __forceinline__ void cpa16(unsigned dst, const void* src) {
    asm volatile("cp.async.cg.shared.global [%0], [%1], 16;" :: "r"(dst), "l"(src));
}
__device__ __forceinline__ void cpcommit() {
    asm volatile("cp.async.commit_group;" ::: "memory");
}
template<int N> __device__ __forceinline__ void cpwait() {
    asm volatile("cp.async.wait_group %0;" :: "n"(N) : "memory");
}
__device__ __forceinline__ unsigned s2u32(const void* p) {
    return (unsigned)__cvta_generic_to_shared(p);
}

// fast exp on the FMA pipe (no MUFU): 2^(x*log2e), deg-5, ~2e-6 rel
__device__ __forceinline__ float fexp(float x) {
    x = fmaxf(x, -87.0f);
    float t  = x * 1.4426950408889634f;
    float fk = t + 12582912.0f;
    int   ki = __float_as_int(fk) - 0x4B400000;
    float r  = t - (fk - 12582912.0f);
    float p  = 1.3333558146e-3f;
    p = fmaf(p, r, 9.6181291076e-3f);
    p = fmaf(p, r, 5.5504108664e-2f);
    p = fmaf(p, r, 2.4022650696e-1f);
    p = fmaf(p, r, 6.9314718056e-1f);
    p = fmaf(p, r, 1.0f);
    return p * __int_as_float((ki + 127) << 23);
}

// ---------------------------------------------------------------------------
// fp32 -> (bf16 hi, bf16 lo) split conversion; grid.y selects source
// ---------------------------------------------------------------------------
__global__ __launch_bounds__(256) void convert_multi(
    const float* __restrict__ p0, const float* __restrict__ p1,
    const float* __restrict__ p2, const float* __restrict__ p3,
    size_t off0, size_t per, size_t n)
{
    int z = blockIdx.y;
    const float* src = (z == 0) ? p0 : (z == 1) ? p1 : (z == 2) ? p2 : p3;
    size_t off = off0 + (size_t)z * per;
    __nv_bfloat16* hp = g_hi + off;
    __nv_bfloat16* lp = g_lo + off;
    size_t i = ((size_t)blockIdx.x * blockDim.x + threadIdx.x) * 4;
    if (i >= n) return;
    float4 v = *(const float4*)(src + i);
    __nv_bfloat16 h0 = __float2bfloat16(v.x), h1 = __float2bfloat16(v.y);
    __nv_bfloat16 h2 = __float2bfloat16(v.z), h3 = __float2bfloat16(v.w);
    __nv_bfloat16 l0 = __float2bfloat16(v.x - __bfloat162float(h0));
    __nv_bfloat16 l1 = __float2bfloat16(v.y - __bfloat162float(h1));
    __nv_bfloat16 l2 = __float2bfloat16(v.z - __bfloat162float(h2));
    __nv_bfloat16 l3 = __float2bfloat16(v.w - __bfloat162float(h3));
    *(ushort4*)(hp + i) = make_ushort4(__bfloat16_as_ushort(h0), __bfloat16_as_ushort(h1),
                                       __bfloat16_as_ushort(h2), __bfloat16_as_ushort(h3));
    *(ushort4*)(lp + i) = make_ushort4(__bfloat16_as_ushort(l0), __bfloat16_as_ushort(l1),
                                       __bfloat16_as_ushort(l2), __bfloat16_as_ushort(l3));
}

// ---------------------------------------------------------------------------
// WMMA bf16x3 GEMM, cp.async double-buffered, one barrier per k-chunk.
// D[128,128] = A[128,K] * B[128,K]^T (K=1024), fp32 accum.
// ---------------------------------------------------------------------------
#define LDS_  72
#define BUFSZ (128 * LDS_)
#define BSBY  (BUFSZ * 2)
#define SM_GEMM_BYTES (8 * BSBY)          // 147456
#define LDD_  68

template<int MODE>
__global__ __launch_bounds__(256) void mma_gemm(
    const float* __restrict__ bias_q, const float* __restrict__ bias_k,
    const float* __restrict__ bias_v, float* __restrict__ Y)
{
    extern __shared__ char smc[];
    __nv_bfloat16* sbf = (__nv_bfloat16*)smc;
    float* Dst = (float*)smc;
    const unsigned smb = s2u32(smc);

    const int tid = threadIdx.x;
    const int wid = tid >> 5;
    const int wm = wid & 3, wn = wid >> 2;
    const int m0 = blockIdx.y * 128, n0 = blockIdx.x * 128;

    size_t aoff, boff;
    const float* bias;
    if (MODE == 0) {
        int z = blockIdx.z;
        aoff = (size_t)z * nX;
        boff = WBASE + (size_t)z * nW;
        bias = (z == 0) ? bias_q : (z == 1) ? bias_k : bias_v;
    } else {
        aoff = AOOFF;
        boff = WBASE + 3 * nW;
        bias = bias_q;   // bo
    }
    const __nv_bfloat16* gAh = g_hi + aoff;
    const __nv_bfloat16* gAl = g_lo + aoff;
    const __nv_bfloat16* gBh = g_hi + boff;
    const __nv_bfloat16* gBl = g_lo + boff;

    auto issue = [&](int kc, int buf) {
        #pragma unroll
        for (int t4 = 0; t4 < 4; t4++) {
            int id = tid + t4 * 256;
            int r  = id >> 3, c8 = id & 7;
            size_t ga = (size_t)(m0 + r) * C_ + kc + c8 * 8;
            size_t gb = (size_t)(n0 + r) * C_ + kc + c8 * 8;
            unsigned so = (r * LDS_ + c8 * 8) * 2;
            cpa16(smb + (0 + buf) * BSBY + so, gAh + ga);
            cpa16(smb + (2 + buf) * BSBY + so, gAl + ga);
            cpa16(smb + (4 + buf) * BSBY + so, gBh + gb);
            cpa16(smb + (6 + buf) * BSBY + so, gBl + gb);
        }
    };

    wmma::fragment<wmma::accumulator, 16, 16, 16, float> acc[2][4];
    #pragma unroll
    for (int i = 0; i < 2; i++)
        #pragma unroll
        for (int j = 0; j < 4; j++)
            wmma::fill_fragment(acc[i][j], 0.0f);

    issue(0, 0);
    cpcommit();

    for (int s = 0; s < 16; s++) {
        const int cur = s & 1;
        cpwait<0>();
        __syncthreads();                 // data[cur] visible; prior reads of cur^1 done
        if (s < 15) { issue((s + 1) * 64, cur ^ 1); cpcommit(); }

        const __nv_bfloat16* Ah = sbf + (0 + cur) * BUFSZ;
        const __nv_bfloat16* Al = sbf + (2 + cur) * BUFSZ;
        const __nv_bfloat16* Bh = sbf + (4 + cur) * BUFSZ;
        const __nv_bfloat16* Bl = sbf + (6 + cur) * BUFSZ;

        #pragma unroll
        for (int ks = 0; ks < 4; ks++) {
            int kk = ks * 16;
            wmma::fragment<wmma::matrix_a, 16, 16, 16, __nv_bfloat16, wmma::row_major> a_hi[2], a_lo[2];
            wmma::fragment<wmma::matrix_b, 16, 16, 16, __nv_bfloat16, wmma::col_major> b_hi[4], b_lo[4];
            #pragma unroll
            for (int i = 0; i < 2; i++) {
                int mrow = wm * 32 + i * 16;
                wmma::load_matrix_sync(a_hi[i], Ah + mrow * LDS_ + kk, LDS_);
                wmma::load_matrix_sync(a_lo[i], Al + mrow * LDS_ + kk, LDS_);
            }
            #pragma unroll
            for (int j = 0; j < 4; j++) {
                int ncol = wn * 64 + j * 16;
                wmma::load_matrix_sync(b_hi[j], Bh + ncol * LDS_ + kk, LDS_);
                wmma::load_matrix_sync(b_lo[j], Bl + ncol * LDS_ + kk, LDS_);
            }
            #pragma unroll
            for (int i = 0; i < 2; i++)
                #pragma unroll
                for (int j = 0; j < 4; j++) {
                    wmma::mma_sync(acc[i][j], a_hi[i], b_hi[j], acc[i][j]);
                    wmma::mma_sync(acc[i][j], a_hi[i], b_lo[j], acc[i][j]);
                    wmma::mma_sync(acc[i][j], a_lo[i], b_hi[j], acc[i][j]);
                }
        }
    }
    __syncthreads();                     // all compute done before Dst aliases buffers

    // Epilogue in two 64-col halves via fp32 smem staging.
    #pragma unroll
    for (int half = 0; half < 2; half++) {
        if (wn == half) {
            #pragma unroll
            for (int i = 0; i < 2; i++)
                #pragma unroll
                for (int j = 0; j < 4; j++)
                    wmma::store_matrix_sync(
                        Dst + (wm * 32 + i * 16) * LDD_ + j * 16,
                        acc[i][j], LDD_, wmma::mem_row_major);
        }
        __syncthreads();
        #pragma unroll
        for (int t = 0; t < 32; t++) {
            int id = tid + t * 256;
            int r = id >> 6, c = id & 63;
            int m = m0 + r;
            int n = n0 + half * 64 + c;
            float v = Dst[r * LDD_ + c] + bias[n];
            if (MODE == 0) {
                int z = blockIdx.z;
                if (z == 0) v *= 0.125f;          // fold 1/sqrt(DK) into Q
                int tt = m >> 2, b = m & 3;       // m = t*B + b
                int hh = n >> 6, d = n & 63;
                __nv_bfloat16 hv = __float2bfloat16(v);
                __nv_bfloat16 lv = __float2bfloat16(v - __bfloat162float(hv));
                size_t base = (z == 0) ? QATT : (z == 1) ? KATT : VATT;
                size_t adr = base + (((size_t)(b * H_ + hh)) * T_ + tt) * DK_ + d;
                g_hi[adr] = hv;
                g_lo[adr] = lv;
            } else {
                Y[(size_t)m * C_ + n] = v;
            }
        }
        __syncthreads();
    }
}

// ---------------------------------------------------------------------------
// FA2 attention: mma.sync bf16x3, cp.async double-buffered 128-key K/V tiles,
// ldmatrix fragment loads, inner loop split into two 64-key halves to halve
// register liveness (S[8][4] instead of S[16][4]) and kill spills.
// ---------------------------------------------------------------------------
#define LQK 72
#define SQ_H   0
#define SQ_L   9216
#define SMEM_ELEMS 92160
#define ATTN_SMEM (SMEM_ELEMS * 2 + 512)

__global__ __launch_bounds__(256, 1) void attn_kernel(const int* __restrict__ mask)
{
    extern __shared__ __nv_bfloat16 sb[];
    unsigned char* ms = (unsigned char*)(sb + SMEM_ELEMS);   // 2 x 128
    const unsigned smb = s2u32(sb);

    const int tid  = threadIdx.x;
    const int lane = tid & 31, wid = tid >> 5;
    const int grp  = lane >> 2, qi = lane & 3;
    const int lrow = lane & 7, lmat = lane >> 3;             // ldmatrix lane roles
    const int bh = blockIdx.y, b = bh >> 4, h = bh & 15;
    const int q0 = blockIdx.x * 128;

    const size_t bho = (size_t)bh * T_ * DK_;
    const __nv_bfloat16* gQh = g_hi + QATT + bho;
    const __nv_bfloat16* gQl = g_lo + QATT + bho;
    const __nv_bfloat16* gKh = g_hi + KATT + bho;
    const __nv_bfloat16* gKl = g_lo + KATT + bho;
    const __nv_bfloat16* gVh = g_hi + VATT + bho;
    const __nv_bfloat16* gVl = g_lo + VATT + bho;

    auto KH = [](int buf) { return 18432 + buf * 9216; };
    auto KL = [](int buf) { return 36864 + buf * 9216; };
    auto VH = [](int buf) { return 55296 + buf * 9216; };
    auto VL = [](int buf) { return 73728 + buf * 9216; };

    auto issueKV = [&](int kt, int buf) {
        #pragma unroll
        for (int i = 0; i < 4; i++) {
            int id = tid + 256 * i, r = id >> 3, c8 = id & 7;
            size_t g = (size_t)(kt * 128 + r) * DK_ + c8 * 8;
            unsigned so = (r * LQK + c8 * 8) * 2;
            cpa16(smb + KH(buf) * 2 + so, gKh + g);
            cpa16(smb + KL(buf) * 2 + so, gKl + g);
            cpa16(smb + VH(buf) * 2 + so, gVh + g);
            cpa16(smb + VL(buf) * 2 + so, gVl + g);
        }
    };

    issueKV(0, 0);
    cpcommit();

    // stage Q while tile-0 copies fly
    #pragma unroll
    for (int i = 0; i < 4; i++) {
        int id = tid + 256 * i, r = id >> 3, c8 = id & 7;
        size_t g = (size_t)(q0 + r) * DK_ + c8 * 8;
        *(uint4*)&sb[SQ_H + r * LQK + c8 * 8] = *(const uint4*)&gQh[g];
        *(uint4*)&sb[SQ_L + r * LQK + c8 * 8] = *(const uint4*)&gQl[g];
    }
    if (tid < 128) ms[tid] = mask[(size_t)b * T_ + tid] ? 1 : 0;   // tile 0 mask -> ms[0]
    __syncthreads();

    unsigned qa_h[4][4], qa_l[4][4];
    {
        int r0 = wid * 16 + grp;
        #pragma unroll
        for (int ks = 0; ks < 4; ks++) {
            int cb = ks * 16 + qi * 2;
            qa_h[ks][0] = *(const unsigned*)&sb[SQ_H + r0 * LQK + cb];
            qa_h[ks][1] = *(const unsigned*)&sb[SQ_H + (r0 + 8) * LQK + cb];
            qa_h[ks][2] = *(const unsigned*)&sb[SQ_H + r0 * LQK + cb + 8];
            qa_h[ks][3] = *(const unsigned*)&sb[SQ_H + (r0 + 8) * LQK + cb + 8];
            qa_l[ks][0] = *(const unsigned*)&sb[SQ_L + r0 * LQK + cb];
            qa_l[ks][1] = *(const unsigned*)&sb[SQ_L + (r0 + 8) * LQK + cb];
            qa_l[ks][2] = *(const unsigned*)&sb[SQ_L + r0 * LQK + cb + 8];
            qa_l[ks][3] = *(const unsigned*)&sb[SQ_L + (r0 + 8) * LQK + cb + 8];
        }
    }

    float O[8][4];
    #pragma unroll
    for (int j = 0; j < 8; j++) O[j][0] = O[j][1] = O[j][2] = O[j][3] = 0.f;
    float mrow0 = -1e30f, mrow1 = -1e30f, lrow0 = 0.f, lrow1 = 0.f;

    for (int kt = 0; kt < 16; kt++) {
        const int cur = kt & 1;
        cpwait<0>();
        __syncthreads();     // tile-cur data + ms[cur] visible; prior reads of cur^1 done

        if (kt < 15) {
            issueKV(kt + 1, cur ^ 1);
            cpcommit();
            if (tid < 128)
                ms[(cur ^ 1) * 128 + tid] = mask[(size_t)b * T_ + (kt + 1) * 128 + tid] ? 1 : 0;
        }
        const unsigned char* mcur = ms + cur * 128;

        #pragma unroll
        for (int half = 0; half < 2; half++) {
            const int kb0 = half * 64;           // key offset within tile

            // ---- S = Q K^T on 64 keys (bf16x3), K frags via ldmatrix.x4 ----
            float S[8][4];
            #pragma unroll
            for (int j = 0; j < 8; j++) S[j][0] = S[j][1] = S[j][2] = S[j][3] = 0.f;
            #pragma unroll
            for (int j = 0; j < 8; j++) {
                unsigned kbh[8], kbl[8];   // [ks*2 + reg]
                unsigned ah = smb + (KH(cur) + (kb0 + j * 8 + lrow) * LQK + lmat * 8) * 2;
                unsigned al = smb + (KL(cur) + (kb0 + j * 8 + lrow) * LQK + lmat * 8) * 2;
                ldm4(kbh,     ah);         // d 0..31  -> ks0,ks1
                ldm4(kbh + 4, ah + 64);    // d 32..63 -> ks2,ks3
                ldm4(kbl,     al);
                ldm4(kbl + 4, al + 64);
                #pragma unroll
                for (int ks = 0; ks < 4; ks++) {
                    mma16816(S[j], qa_h[ks], kbh + ks * 2);
                    mma16816(S[j], qa_h[ks], kbl + ks * 2);
                    mma16816(S[j], qa_l[ks], kbh + ks * 2);
                }
            }

            // ---- mask + online softmax over this 64-key half ----
            float ml0 = -3e38f, ml1 = -3e38f;
            #pragma unroll
            for (int j = 0; j < 8; j++) {
                if (mcur[kb0 + j * 8 + qi * 2])     { S[j][0] = -1e30f; S[j][2] = -1e30f; }
                if (mcur[kb0 + j * 8 + qi * 2 + 1]) { S[j][1] = -1e30f; S[j][3] = -1e30f; }
                ml0 = fmaxf(ml0, fmaxf(S[j][0], S[j][1]));
                ml1 = fmaxf(ml1, fmaxf(S[j][2], S[j][3]));
            }
            ml0 = fmaxf(ml0, __shfl_xor_sync(0xffffffffu, ml0, 1));
            ml0 = fmaxf(ml0, __shfl_xor_sync(0xffffffffu, ml0, 2));
            ml1 = fmaxf(ml1, __shfl_xor_sync(0xffffffffu, ml1, 1));
            ml1 = fmaxf(ml1, __shfl_xor_sync(0xffffffffu, ml1, 2));

            float mN0 = fmaxf(mrow0, ml0), mN1 = fmaxf(mrow1, ml1);
            float f0 = fexp(mrow0 - mN0), f1 = fexp(mrow1 - mN1);
            mrow0 = mN0; mrow1 = mN1;

            float ps0 = 0.f, ps1 = 0.f;
            #pragma unroll
            for (int j = 0; j < 8; j++) {
                S[j][0] = fexp(S[j][0] - mN0);
                S[j][1] = fexp(S[j][1] - mN0);
                S[j][2] = fexp(S[j][2] - mN1);
                S[j][3] = fexp(S[j][3] - mN1);
                ps0 += S[j][0] + S[j][1];
                ps1 += S[j][2] + S[j][3];
            }
            ps0 += __shfl_xor_sync(0xffffffffu, ps0, 1);
            ps0 += __shfl_xor_sync(0xffffffffu, ps0, 2);
            ps1 += __shfl_xor_sync(0xffffffffu, ps1, 1);
            ps1 += __shfl_xor_sync(0xffffffffu, ps1, 2);
            lrow0 = lrow0 * f0 + ps0;
            lrow1 = lrow1 * f1 + ps1;
            #pragma unroll
            for (int j = 0; j < 8; j++) {
                O[j][0] *= f0; O[j][1] *= f0; O[j][2] *= f1; O[j][3] *= f1;
            }

            // ---- O += P V on 64 keys; V frags via ldmatrix.x4.trans ----
            #pragma unroll
            for (int s = 0; s < 4; s++) {
                const float* ca = S[2 * s];
                const float* cb = S[2 * s + 1];
                unsigned pah[4], pal[4];
                pah[0] = packbf(ca[0], ca[1]);
                pah[1] = packbf(ca[2], ca[3]);
                pah[2] = packbf(cb[0], cb[1]);
                pah[3] = packbf(cb[2], cb[3]);
                pal[0] = packbf(ca[0] - lobf(pah[0]), ca[1] - hibf(pah[0]));
                pal[1] = packbf(ca[2] - lobf(pah[1]), ca[3] - hibf(pah[1]));
                pal[2] = packbf(cb[0] - lobf(pah[2]), cb[1] - hibf(pah[2]));
                pal[3] = packbf(cb[2] - lobf(pah[3]), cb[3] - hibf(pah[3]));

                unsigned vbh[16], vbl[16];  // [j*2 + reg], j = d-block 0..7
                #pragma unroll
                for (int jp = 0; jp < 4; jp++) {
                    unsigned av = smb + (VH(cur) + (kb0 + s * 16 + (lmat & 1) * 8 + lrow) * LQK
                                        + (jp * 2 + (lmat >> 1)) * 8) * 2;
                    unsigned al = smb + (VL(cur) + (kb0 + s * 16 + (lmat & 1) * 8 + lrow) * LQK
                                        + (jp * 2 + (lmat >> 1)) * 8) * 2;
                    ldm4t(vbh + jp * 4, av);
                    ldm4t(vbl + jp * 4, al);
                }
                #pragma unroll
                for (int j = 0; j < 8; j++) {
                    mma16816(O[j], pah, vbh + j * 2);
                    mma16816(O[j], pah, vbl + j * 2);
                    mma16816(O[j], pal, vbh + j * 2);
                }
            }
        }
    }

    // ---- epilogue ----
    float inv0 = 1.0f / lrow0, inv1 = 1.0f / lrow1;
    int r0g = q0 + wid * 16 + grp;
    __nv_bfloat16* aoh = g_hi + AOOFF;
    __nv_bfloat16* aol = g_lo + AOOFF;
    #pragma unroll
    for (int j = 0; j < 8; j++) {
        int col = h * 64 + j * 8 + qi * 2;
        float v0 = O[j][0] * inv0, v1 = O[j][1] * inv0;
        unsigned hp = packbf(v0, v1);
        unsigned lp = packbf(v0 - lobf(hp), v1 - hibf(hp));
        size_t a0 = (size_t)(r0g * B_ + b) * C_ + col;
        *(unsigned*)&aoh[a0] = hp;
        *(unsigned*)&aol[a0] = lp;
        float v2 = O[j][2] * inv1, v3 = O[j][3] * inv1;
        hp = packbf(v2, v3);
        lp = packbf(v2 - lobf(hp), v3 - hibf(hp));
        size_t a1 = (size_t)((r0g + 8) * B_ + b) * C_ + col;
        *(unsigned*)&aoh[a1] = hp;
        *(unsigned*)&aol[a1] = lp;
    }
}

// ---------------------------------------------------------------------------
extern "C" void kernel_launch(void* const* d_in, const int* in_sizes, int n_in,
                              void* d_out, int out_size)
{
    const float* query = (const float*)d_in[0];
    const float* key   = (const float*)d_in[1];
    const float* value = (const float*)d_in[2];
    const int*   mask  = (const int*)d_in[3];
    const float* Wq = (const float*)d_in[4];
    const float* bq = (const float*)d_in[5];
    const float* Wk = (const float*)d_in[6];
    const float* bk = (const float*)d_in[7];
    const float* Wv = (const float*)d_in[8];
    const float* bv = (const float*)d_in[9];
    const float* Wo = (const float*)d_in[10];
    const float* bo = (const float*)d_in[11];
    float* out = (float*)d_out;

    convert_multi<<<dim3((unsigned)(nX / 1024), 3), 256>>>(
        query, key, value, nullptr, 0, nX, nX);
    convert_multi<<<dim3((unsigned)(nW / 1024), 4), 256>>>(
        Wq, Wk, Wv, Wo, WBASE, nW, nW);

    cudaFuncSetAttribute(mma_gemm<0>, cudaFuncAttributeMaxDynamicSharedMemorySize, SM_GEMM_BYTES);
    cudaFuncSetAttribute(mma_gemm<1>, cudaFuncAttributeMaxDynamicSharedMemorySize, SM_GEMM_BYTES);
    cudaFuncSetAttribute(attn_kernel, cudaFuncAttributeMaxDynamicSharedMemorySize, ATTN_SMEM);

    mma_gemm<0><<<dim3(C_ / 128, M_ / 128, 3), 256, SM_GEMM_BYTES>>>(bq, bk, bv, nullptr);
    attn_kernel<<<dim3(T_ / 128, B_ * H_), 256, ATTN_SMEM>>>(mask);
    mma_gemm<1><<<dim3(C_ / 128, M_ / 128, 1), 256, SM_GEMM_BYTES>>>(bo, nullptr, nullptr, out);
}